// round 4
// baseline (speedup 1.0000x reference)
#include <cuda_runtime.h>
#include <math.h>

#define BB 32
#define LL 52
#define VV 10000
#define HH 512
#define ENCK 401408
#define TT 51
#define G4 2048
#define KSPLIT 74
#define KCHUNK 5440

__device__ int   g_sort[BB];
__device__ int   g_declen[BB];
__device__ int   g_caps[BB*LL];
__device__ float g_part[(long long)KSPLIT*BB*HH];
__device__ float g_x0bn[BB*HH];
__device__ float g_xw[(long long)LL*BB*G4];
__device__ float g_hbuf[2][BB*HH];
__device__ float g_cbuf[BB*HH];
__device__ float g_h2[(long long)TT*BB*HH];

__global__ void k0_setup(const int* __restrict__ caps, const int* __restrict__ lens,
                         float* __restrict__ out, long long out_size) {
    int t = threadIdx.x;
    if (t == 0) {
        int len[BB]; bool used[BB];
        for (int i = 0; i < BB; i++) { len[i] = lens[i]; used[i] = false; }
        for (int r = 0; r < BB; r++) {
            int best = -1;
            for (int i = 0; i < BB; i++)
                if (!used[i] && (best < 0 || len[i] > len[best])) best = i;
            used[best] = true; g_sort[r] = best; g_declen[r] = len[best] - 1;
        }
    }
    __syncthreads();
    long long P = (long long)BB * TT * VV;
    for (int i = t; i < BB*LL; i += blockDim.x) {
        int b = i / LL, c = i % LL;
        int v = caps[g_sort[b]*LL + c];
        g_caps[i] = v;
        if (P + i < out_size) out[P + i] = (float)v;
    }
    for (int i = t; i < 2*BB*HH; i += blockDim.x) ((float*)g_hbuf)[i] = 0.f;
    for (int i = t; i < BB*HH;   i += blockDim.x) g_cbuf[i] = 0.f;
    for (int i = t; i < BB; i += blockDim.x) {
        if (P + BB*LL + i      < out_size) out[P + BB*LL + i]      = (float)g_declen[i];
        if (P + BB*LL + BB + i < out_size) out[P + BB*LL + BB + i] = (float)g_sort[i];
    }
}

__device__ __forceinline__ float4 ldg4g(const float* p, int k, int kmax) {
    float4 v = make_float4(0.f,0.f,0.f,0.f);
    if (k + 3 < kmax) v = *(const float4*)(p + k);
    else {
        if (k   < kmax) v.x = p[k];
        if (k+1 < kmax) v.y = p[k+1];
        if (k+2 < kmax) v.z = p[k+2];
        if (k+3 < kmax) v.w = p[k+3];
    }
    return v;
}

// x0 partials: enc_sorted(32 x ENCK) @ init_w.T(ENCK x 512), split-K
__global__ __launch_bounds__(256) void k1_initgemm(const float* __restrict__ enc,
                                                   const float* __restrict__ w) {
    __shared__ float es[32][33];
    __shared__ float ws[32][68];   // row stride multiple of 4 -> aligned float4 reads
    int t = threadIdx.x;
    int n0 = blockIdx.x * 64;
    int kbase = blockIdx.y * KCHUNK;
    int lb = t >> 3, lko = (t & 7) * 4;
    const float* erow = enc + (long long)g_sort[lb] * ENCK;
    int wn = t >> 2, wko = (t & 3) * 8;
    const float* wrow = w + (long long)(n0 + wn) * ENCK;
    int b2 = (t >> 4) * 2, n4 = (t & 15) * 4;
    float acc[2][4] = {};
    for (int kt = 0; kt < KCHUNK; kt += 32) {
        int k0 = kbase + kt;
        float4 v = ldg4g(erow, k0 + lko, ENCK);
        es[lko][lb]=v.x; es[lko+1][lb]=v.y; es[lko+2][lb]=v.z; es[lko+3][lb]=v.w;
#pragma unroll
        for (int h = 0; h < 2; h++) {
            int kk = wko + h*4;
            float4 u = ldg4g(wrow, k0 + kk, ENCK);
            ws[kk][wn]=u.x; ws[kk+1][wn]=u.y; ws[kk+2][wn]=u.z; ws[kk+3][wn]=u.w;
        }
        __syncthreads();
#pragma unroll
        for (int k = 0; k < 32; k++) {
            float e0 = es[k][b2], e1 = es[k][b2+1];
            float4 wv = *(const float4*)&ws[k][n4];
            acc[0][0]+=e0*wv.x; acc[0][1]+=e0*wv.y; acc[0][2]+=e0*wv.z; acc[0][3]+=e0*wv.w;
            acc[1][0]+=e1*wv.x; acc[1][1]+=e1*wv.y; acc[1][2]+=e1*wv.z; acc[1][3]+=e1*wv.w;
        }
        __syncthreads();
    }
#pragma unroll
    for (int i = 0; i < 2; i++) {
        float* p = g_part + ((long long)blockIdx.y * BB + b2 + i) * HH + n0 + n4;
        p[0]=acc[i][0]; p[1]=acc[i][1]; p[2]=acc[i][2]; p[3]=acc[i][3];
    }
}

// reduce partials + bias + batchnorm(batch axis, 32)
__global__ void k2_bn(const float* __restrict__ bias, const float* __restrict__ gamma,
                      const float* __restrict__ beta) {
    int n = blockIdx.x, t = threadIdx.x;
    int b = t & 31, grp = t >> 5;
    float s = 0.f;
    for (int ks = grp; ks < KSPLIT; ks += 4)
        s += g_part[((long long)ks * BB + b) * HH + n];
    __shared__ float red[128];
    red[t] = s; __syncthreads();
    if (t < 32) {
        float x = red[t] + red[t+32] + red[t+64] + red[t+96] + bias[n];
        float sum = x, sq = x * x;
#pragma unroll
        for (int o = 16; o > 0; o >>= 1) {
            sum += __shfl_xor_sync(0xffffffffu, sum, o);
            sq  += __shfl_xor_sync(0xffffffffu, sq,  o);
        }
        float mu = sum * (1.f/32.f);
        float var = sq * (1.f/32.f) - mu * mu;
        g_x0bn[b * HH + n] = (x - mu) * rsqrtf(var + 1e-5f) * gamma[n] + beta[n];
    }
}

// XW: [x0_bn; emb tokens](1664 x 512) @ w_ih.T + (b_ih + b_hh)
__global__ __launch_bounds__(256) void k4_xw(const float* __restrict__ embw,
                                             const float* __restrict__ wih,
                                             const float* __restrict__ bih,
                                             const float* __restrict__ bhh) {
    __shared__ float As[16][132];
    __shared__ float Bs[16][68];
    int t = threadIdx.x;
    int m0 = blockIdx.x * 128, n0 = blockIdx.y * 64;
    int am = t >> 1, ako = (t & 1) * 8;
    int r = m0 + am;
    const float* arow;
    if (r < BB) arow = g_x0bn + r * HH;
    else { int rr = r - BB; arow = embw + (long long)g_caps[(rr & 31) * LL + (rr >> 5)] * HH; }
    int bn = t & 63, bko = (t >> 6) * 4;
    const float* brow = wih + (long long)(n0 + bn) * HH;
    int m8 = (t >> 4) * 8, n4 = (t & 15) * 4;
    float acc[8][4] = {};
    for (int k0 = 0; k0 < HH; k0 += 16) {
        float4 a0 = *(const float4*)(arow + k0 + ako);
        float4 a1 = *(const float4*)(arow + k0 + ako + 4);
        As[ako][am]=a0.x; As[ako+1][am]=a0.y; As[ako+2][am]=a0.z; As[ako+3][am]=a0.w;
        As[ako+4][am]=a1.x; As[ako+5][am]=a1.y; As[ako+6][am]=a1.z; As[ako+7][am]=a1.w;
        float4 bv = *(const float4*)(brow + k0 + bko);
        Bs[bko][bn]=bv.x; Bs[bko+1][bn]=bv.y; Bs[bko+2][bn]=bv.z; Bs[bko+3][bn]=bv.w;
        __syncthreads();
#pragma unroll
        for (int k = 0; k < 16; k++) {
            float4 x0 = *(const float4*)&As[k][m8];
            float4 x1 = *(const float4*)&As[k][m8+4];
            float4 y  = *(const float4*)&Bs[k][n4];
            float xa[8] = {x0.x,x0.y,x0.z,x0.w,x1.x,x1.y,x1.z,x1.w};
#pragma unroll
            for (int i = 0; i < 8; i++) {
                acc[i][0]+=xa[i]*y.x; acc[i][1]+=xa[i]*y.y;
                acc[i][2]+=xa[i]*y.z; acc[i][3]+=xa[i]*y.w;
            }
        }
        __syncthreads();
    }
#pragma unroll
    for (int i = 0; i < 8; i++) {
        float* o = g_xw + (long long)(m0 + m8 + i) * G4 + n0 + n4;
#pragma unroll
        for (int j = 0; j < 4; j++) o[j] = acc[i][j] + bih[n0+n4+j] + bhh[n0+n4+j];
    }
}

// one LSTM cell: block = 4 cols x 4 gates x 32 b; grid 128
__global__ __launch_bounds__(128) void k5_step(const float* __restrict__ whh, int cell) {
    extern __shared__ float dyn[];
    float* hs = dyn;              // [512][32]
    float* ws = dyn + 512 * 32;   // [512][16]
    __shared__ float gs[16][33];
    int t = threadIdx.x;
    int c0 = blockIdx.x * 4;
    const float* hprev = g_hbuf[cell & 1];
    {   // h -> transposed shared
        int lb = t >> 2, ko = (t & 3) * 4;
        const float* hp = hprev + lb * HH;
#pragma unroll
        for (int i = 0; i < 32; i++) {
            int k = ko + i * 16;
            float4 v = *(const float4*)(hp + k);
            hs[(k  )*32+lb]=v.x; hs[(k+1)*32+lb]=v.y;
            hs[(k+2)*32+lb]=v.z; hs[(k+3)*32+lb]=v.w;
        }
    }
    {   // 16 w_hh rows: rl = g*4+j  <->  R = g*512 + c0 + j
        int rl = t >> 3;
        const float* wp = whh + (long long)((rl >> 2) * 512 + c0 + (rl & 3)) * HH;
        int ko = (t & 7) * 4;
#pragma unroll
        for (int i = 0; i < 16; i++) {
            int k = ko + i * 32;
            float4 v = *(const float4*)(wp + k);
            ws[(k  )*16+rl]=v.x; ws[(k+1)*16+rl]=v.y;
            ws[(k+2)*16+rl]=v.z; ws[(k+3)*16+rl]=v.w;
        }
    }
    __syncthreads();
    {   // dots: thread = 2b x 2r
        int r2 = (t & 7) * 2, b2 = (t >> 3) * 2;
        float a00=0.f,a01=0.f,a10=0.f,a11=0.f;
#pragma unroll 8
        for (int k = 0; k < 512; k++) {
            float2 hv = *(const float2*)&hs[k*32 + b2];
            float2 wv = *(const float2*)&ws[k*16 + r2];
            a00 += hv.x*wv.x; a01 += hv.x*wv.y;
            a10 += hv.y*wv.x; a11 += hv.y*wv.y;
        }
        gs[r2  ][b2]=a00; gs[r2+1][b2]=a01;
        gs[r2  ][b2+1]=a10; gs[r2+1][b2+1]=a11;
    }
    __syncthreads();
    {   // elementwise
        int b = t & 31, j = t >> 5;
        int col = c0 + j;
        const float* xw = g_xw + ((long long)cell * BB + b) * G4;
        float iv = gs[0*4+j][b] + xw[          col];
        float fv = gs[1*4+j][b] + xw[  512 +   col];
        float gv = gs[2*4+j][b] + xw[2*512 +   col];
        float ov = gs[3*4+j][b] + xw[3*512 +   col];
        float si = 1.f/(1.f+expf(-iv)), sf = 1.f/(1.f+expf(-fv));
        float so = 1.f/(1.f+expf(-ov)), tg = tanhf(gv);
        int ci = b * HH + col;
        float cold = g_cbuf[ci];
        float cn = sf * cold + si * tg;
        float hn = so * tanhf(cn);
        bool act = (cell == 0) || (g_declen[b] > (cell - 1));
        g_cbuf[ci] = act ? cn : cold;
        g_hbuf[(cell + 1) & 1][ci] = act ? hn : hprev[ci];
        if (cell >= 1)
            g_h2[((long long)(cell - 1) * BB + b) * HH + col] = hn;
    }
}

// predictions = mask( H2(1632x512) @ fc_w.T + fc_b )
__global__ __launch_bounds__(256) void k6_fc(const float* __restrict__ fcw,
                                             const float* __restrict__ fcb,
                                             float* __restrict__ out, long long out_size) {
    __shared__ float As[16][132];
    __shared__ float Bs[16][68];
    int t = threadIdx.x;
    int m0 = blockIdx.x * 128, n0 = blockIdx.y * 64;
    const int M = TT * BB;
    int am = t >> 1, ako = (t & 1) * 8;
    int r = m0 + am; if (r >= M) r = 0;
    const float* arow = g_h2 + (long long)r * HH;
    int bn = t & 63, bko = (t >> 6) * 4;
    int bnc = n0 + bn; if (bnc >= VV) bnc = VV - 1;
    const float* brow = fcw + (long long)bnc * HH;
    int m8 = (t >> 4) * 8, n4 = (t & 15) * 4;
    float acc[8][4] = {};
    for (int k0 = 0; k0 < HH; k0 += 16) {
        float4 a0 = *(const float4*)(arow + k0 + ako);
        float4 a1 = *(const float4*)(arow + k0 + ako + 4);
        As[ako][am]=a0.x; As[ako+1][am]=a0.y; As[ako+2][am]=a0.z; As[ako+3][am]=a0.w;
        As[ako+4][am]=a1.x; As[ako+5][am]=a1.y; As[ako+6][am]=a1.z; As[ako+7][am]=a1.w;
        float4 bv = *(const float4*)(brow + k0 + bko);
        Bs[bko][bn]=bv.x; Bs[bko+1][bn]=bv.y; Bs[bko+2][bn]=bv.z; Bs[bko+3][bn]=bv.w;
        __syncthreads();
#pragma unroll
        for (int k = 0; k < 16; k++) {
            float4 x0 = *(const float4*)&As[k][m8];
            float4 x1 = *(const float4*)&As[k][m8+4];
            float4 y  = *(const float4*)&Bs[k][n4];
            float xa[8] = {x0.x,x0.y,x0.z,x0.w,x1.x,x1.y,x1.z,x1.w};
#pragma unroll
            for (int i = 0; i < 8; i++) {
                acc[i][0]+=xa[i]*y.x; acc[i][1]+=xa[i]*y.y;
                acc[i][2]+=xa[i]*y.z; acc[i][3]+=xa[i]*y.w;
            }
        }
        __syncthreads();
    }
#pragma unroll
    for (int i = 0; i < 8; i++) {
        int rr = m0 + m8 + i;
        if (rr >= M) continue;
        int tt = rr >> 5, bb = rr & 31;
        bool act = g_declen[bb] > tt;
#pragma unroll
        for (int j = 0; j < 4; j++) {
            int col = n0 + n4 + j;
            if (col >= VV) continue;
            long long idx = (long long)bb * TT * VV + (long long)tt * VV + col;
            if (idx < out_size) out[idx] = act ? (acc[i][j] + fcb[col]) : 0.f;
        }
    }
}

extern "C" void kernel_launch(void* const* d_in, const int* in_sizes, int n_in,
                              void* d_out, int out_size) {
    const float* enc   = (const float*)d_in[0];
    const int*   caps  = (const int*)  d_in[1];
    const int*   lens  = (const int*)  d_in[2];
    const float* embw  = (const float*)d_in[3];
    const float* initw = (const float*)d_in[4];
    const float* initb = (const float*)d_in[5];
    const float* gamma = (const float*)d_in[6];
    const float* beta  = (const float*)d_in[7];
    const float* wih   = (const float*)d_in[8];
    const float* whh   = (const float*)d_in[9];
    const float* bih   = (const float*)d_in[10];
    const float* bhh   = (const float*)d_in[11];
    const float* fcw   = (const float*)d_in[12];
    const float* fcb   = (const float*)d_in[13];
    float* out = (float*)d_out;
    long long osz = (long long)out_size;

    cudaFuncSetAttribute(k5_step, cudaFuncAttributeMaxDynamicSharedMemorySize, 98304);

    k0_setup<<<1, 256>>>(caps, lens, out, osz);
    k1_initgemm<<<dim3(8, KSPLIT), 256>>>(enc, initw);
    k2_bn<<<512, 128>>>(initb, gamma, beta);
    k4_xw<<<dim3(13, 32), 256>>>(embw, wih, bih, bhh);
    for (int cell = 0; cell < LL; cell++)
        k5_step<<<128, 128, 98304>>>(whh, cell);
    k6_fc<<<dim3(13, 157), 256>>>(fcw, fcb, out, osz);
}

// round 5
// speedup vs baseline: 1.0434x; 1.0434x over previous
#include <cuda_runtime.h>
#include <mma.h>
#include <math.h>

using namespace nvcuda;

#define BB 32
#define LL 52
#define VV 10000
#define HH 512
#define ENCK 401408
#define TT 51
#define G4 2048
#define KSPLIT 148
#define KCHUNK 2720

__device__ int   g_sort[BB];
__device__ int   g_declen[BB];
__device__ int   g_caps[BB*LL];
__device__ float g_part[(long long)KSPLIT*BB*HH];
__device__ float g_x0bn[BB*HH];
__device__ float g_xw[(long long)LL*BB*G4];
__device__ float g_hbuf[2][BB*HH];
__device__ float g_cbuf[BB*HH];
__device__ float g_h2[(long long)TT*BB*HH];

__global__ void k0_setup(const int* __restrict__ caps, const int* __restrict__ lens,
                         float* __restrict__ out, long long out_size) {
    int t = threadIdx.x;
    if (t == 0) {
        int len[BB]; bool used[BB];
        for (int i = 0; i < BB; i++) { len[i] = lens[i]; used[i] = false; }
        for (int r = 0; r < BB; r++) {
            int best = -1;
            for (int i = 0; i < BB; i++)
                if (!used[i] && (best < 0 || len[i] > len[best])) best = i;
            used[best] = true; g_sort[r] = best; g_declen[r] = len[best] - 1;
        }
    }
    __syncthreads();
    long long P = (long long)BB * TT * VV;
    for (int i = t; i < BB*LL; i += blockDim.x) {
        int b = i / LL, c = i % LL;
        int v = caps[g_sort[b]*LL + c];
        g_caps[i] = v;
        if (P + i < out_size) out[P + i] = (float)v;
    }
    for (int i = t; i < 2*BB*HH; i += blockDim.x) ((float*)g_hbuf)[i] = 0.f;
    for (int i = t; i < BB*HH;   i += blockDim.x) g_cbuf[i] = 0.f;
    for (int i = t; i < BB; i += blockDim.x) {
        if (P + BB*LL + i      < out_size) out[P + BB*LL + i]      = (float)g_declen[i];
        if (P + BB*LL + BB + i < out_size) out[P + BB*LL + BB + i] = (float)g_sort[i];
    }
}

__device__ __forceinline__ float4 ldg4g(const float* p, int k, int kmax) {
    float4 v = make_float4(0.f,0.f,0.f,0.f);
    if (k + 3 < kmax) v = *(const float4*)(p + k);
    else {
        if (k   < kmax) v.x = p[k];
        if (k+1 < kmax) v.y = p[k+1];
        if (k+2 < kmax) v.z = p[k+2];
        if (k+3 < kmax) v.w = p[k+3];
    }
    return v;
}

// ---- k1: x0 partials via TF32 wmma. One block per K-split; block covers all N=512.
// block 256 thr = 8 warps; warp tile m32 x n64 (2x4 frags). k-chunk 16.
__global__ __launch_bounds__(256) void k1_initgemm(const float* __restrict__ enc,
                                                   const float* __restrict__ w) {
    __shared__ float As[32*20];    // [m][k] row-major, lda 20
    __shared__ float Bs[512*20];   // col-major (k,n): [n][k], ldb 20
    int t = threadIdx.x;
    int wid = t >> 5;
    int kbase = blockIdx.x * KCHUNK;
    int am = t >> 3, aq = t & 7;
    const float* arow = enc + (long long)g_sort[am] * ENCK;

    wmma::fragment<wmma::accumulator,16,16,8,float> acc[2][4];
#pragma unroll
    for (int mi = 0; mi < 2; mi++)
#pragma unroll
        for (int nj = 0; nj < 4; nj++) wmma::fill_fragment(acc[mi][nj], 0.f);

    for (int kt = 0; kt < KCHUNK; kt += 16) {
        int k0 = kbase + kt;
        {   // A 32x16
            int kk = k0 + aq*2;
            float2 v = make_float2(0.f, 0.f);
            if (kk + 1 < ENCK) v = *(const float2*)(arow + kk);
            else if (kk < ENCK) v.x = arow[kk];
            *(float2*)&As[am*20 + aq*2] = v;
        }
#pragma unroll
        for (int i = 0; i < 8; i++) {   // B 512x16
            int idx = t + i*256;
            int n = idx >> 2, q = idx & 3;
            float4 u = ldg4g(w + (long long)n * ENCK, k0 + q*4, ENCK);
            *(float4*)&Bs[n*20 + q*4] = u;
        }
        __syncthreads();
#pragma unroll
        for (int ks = 0; ks < 2; ks++) {
            wmma::fragment<wmma::matrix_a,16,16,8,wmma::precision::tf32,wmma::row_major> af[2];
            wmma::fragment<wmma::matrix_b,16,16,8,wmma::precision::tf32,wmma::col_major> bf[4];
#pragma unroll
            for (int mi = 0; mi < 2; mi++) {
                wmma::load_matrix_sync(af[mi], &As[(mi*16)*20 + ks*8], 20);
#pragma unroll
                for (int e = 0; e < af[mi].num_elements; e++)
                    af[mi].x[e] = wmma::__float_to_tf32(af[mi].x[e]);
            }
#pragma unroll
            for (int nj = 0; nj < 4; nj++) {
                wmma::load_matrix_sync(bf[nj], &Bs[(wid*64 + nj*16)*20 + ks*8], 20);
#pragma unroll
                for (int e = 0; e < bf[nj].num_elements; e++)
                    bf[nj].x[e] = wmma::__float_to_tf32(bf[nj].x[e]);
            }
#pragma unroll
            for (int mi = 0; mi < 2; mi++)
#pragma unroll
                for (int nj = 0; nj < 4; nj++)
                    wmma::mma_sync(acc[mi][nj], af[mi], bf[nj], acc[mi][nj]);
        }
        __syncthreads();
    }
    float* base = g_part + (long long)blockIdx.x * BB * HH;
#pragma unroll
    for (int mi = 0; mi < 2; mi++)
#pragma unroll
        for (int nj = 0; nj < 4; nj++)
            wmma::store_matrix_sync(base + mi*16*HH + wid*64 + nj*16,
                                    acc[mi][nj], HH, wmma::mem_row_major);
}

// reduce partials + bias + batchnorm(batch axis, 32)
__global__ void k2_bn(const float* __restrict__ bias, const float* __restrict__ gamma,
                      const float* __restrict__ beta) {
    int n = blockIdx.x, t = threadIdx.x;
    int b = t & 31, grp = t >> 5;
    float s = 0.f;
    for (int ks = grp; ks < KSPLIT; ks += 4)
        s += g_part[((long long)ks * BB + b) * HH + n];
    __shared__ float red[128];
    red[t] = s; __syncthreads();
    if (t < 32) {
        float x = red[t] + red[t+32] + red[t+64] + red[t+96] + bias[n];
        float sum = x, sq = x * x;
#pragma unroll
        for (int o = 16; o > 0; o >>= 1) {
            sum += __shfl_xor_sync(0xffffffffu, sum, o);
            sq  += __shfl_xor_sync(0xffffffffu, sq,  o);
        }
        float mu = sum * (1.f/32.f);
        float var = sq * (1.f/32.f) - mu * mu;
        g_x0bn[b * HH + n] = (x - mu) * rsqrtf(var + 1e-5f) * gamma[n] + beta[n];
    }
}

// ---- k4: XW = [x0_bn; emb](1664x512) @ w_ih.T + bias via TF32 wmma
// block tile 64m x 128n, 8 warps (2x4) of 32x32, k-chunk 32
__global__ __launch_bounds__(256) void k4_xw(const float* __restrict__ embw,
                                             const float* __restrict__ wih,
                                             const float* __restrict__ bih,
                                             const float* __restrict__ bhh) {
    __shared__ float sm[8448];           // As 64x36 | Bs 128x36 ; reused as sC 64x132
    float* As = sm;                      // lda 36
    float* Bs = sm + 64*36;              // ldb 36 (col-major [n][k])
    int t = threadIdx.x;
    int wid = t >> 5, wm = wid >> 2, wn = wid & 3;
    int m0 = blockIdx.x * 64, n0 = blockIdx.y * 128;

    const float* arp[2];
#pragma unroll
    for (int i = 0; i < 2; i++) {
        int r = m0 + ((t + i*256) >> 3);
        if (r < BB) arp[i] = g_x0bn + r * HH;
        else { int rr = r - BB; arp[i] = embw + (long long)g_caps[(rr & 31)*LL + (rr >> 5)] * HH; }
    }
    const float* brp[4];
#pragma unroll
    for (int i = 0; i < 4; i++)
        brp[i] = wih + (long long)(n0 + ((t + i*256) >> 3)) * HH;

    wmma::fragment<wmma::accumulator,16,16,8,float> acc[2][2];
#pragma unroll
    for (int mi = 0; mi < 2; mi++)
#pragma unroll
        for (int nj = 0; nj < 2; nj++) wmma::fill_fragment(acc[mi][nj], 0.f);

    for (int k0 = 0; k0 < HH; k0 += 32) {
#pragma unroll
        for (int i = 0; i < 2; i++) {
            int idx = t + i*256, row = idx >> 3, q = idx & 7;
            *(float4*)&As[row*36 + q*4] = *(const float4*)(arp[i] + k0 + q*4);
        }
#pragma unroll
        for (int i = 0; i < 4; i++) {
            int idx = t + i*256, n = idx >> 3, q = idx & 7;
            *(float4*)&Bs[n*36 + q*4] = *(const float4*)(brp[i] + k0 + q*4);
        }
        __syncthreads();
#pragma unroll
        for (int ks = 0; ks < 4; ks++) {
            wmma::fragment<wmma::matrix_a,16,16,8,wmma::precision::tf32,wmma::row_major> af[2];
            wmma::fragment<wmma::matrix_b,16,16,8,wmma::precision::tf32,wmma::col_major> bf[2];
#pragma unroll
            for (int mi = 0; mi < 2; mi++) {
                wmma::load_matrix_sync(af[mi], &As[(wm*32 + mi*16)*36 + ks*8], 36);
#pragma unroll
                for (int e = 0; e < af[mi].num_elements; e++)
                    af[mi].x[e] = wmma::__float_to_tf32(af[mi].x[e]);
            }
#pragma unroll
            for (int nj = 0; nj < 2; nj++) {
                wmma::load_matrix_sync(bf[nj], &Bs[(wn*32 + nj*16)*36 + ks*8], 36);
#pragma unroll
                for (int e = 0; e < bf[nj].num_elements; e++)
                    bf[nj].x[e] = wmma::__float_to_tf32(bf[nj].x[e]);
            }
#pragma unroll
            for (int mi = 0; mi < 2; mi++)
#pragma unroll
                for (int nj = 0; nj < 2; nj++)
                    wmma::mma_sync(acc[mi][nj], af[mi], bf[nj], acc[mi][nj]);
        }
        __syncthreads();
    }
    float* sC = sm;   // 64 x 132
#pragma unroll
    for (int mi = 0; mi < 2; mi++)
#pragma unroll
        for (int nj = 0; nj < 2; nj++)
            wmma::store_matrix_sync(&sC[(wm*32 + mi*16)*132 + wn*32 + nj*16],
                                    acc[mi][nj], 132, wmma::mem_row_major);
    __syncthreads();
#pragma unroll
    for (int j = 0; j < 32; j++) {
        int e = t + j*256;
        int row = e >> 7, cl = e & 127;
        int col = n0 + cl;
        g_xw[(long long)(m0 + row) * G4 + col] = sC[row*132 + cl] + bih[col] + bhh[col];
    }
}

// one LSTM cell: block = 4 cols x 4 gates x 32 b; grid 128
__global__ __launch_bounds__(128) void k5_step(const float* __restrict__ whh, int cell) {
    extern __shared__ float dyn[];
    float* hs = dyn;              // [512][32]
    float* ws = dyn + 512 * 32;   // [512][16]
    __shared__ float gs[16][33];
    int t = threadIdx.x;
    int c0 = blockIdx.x * 4;
    const float* hprev = g_hbuf[cell & 1];
    {
        int lb = t >> 2, ko = (t & 3) * 4;
        const float* hp = hprev + lb * HH;
#pragma unroll
        for (int i = 0; i < 32; i++) {
            int k = ko + i * 16;
            float4 v = *(const float4*)(hp + k);
            hs[(k  )*32+lb]=v.x; hs[(k+1)*32+lb]=v.y;
            hs[(k+2)*32+lb]=v.z; hs[(k+3)*32+lb]=v.w;
        }
    }
    {
        int rl = t >> 3;
        const float* wp = whh + (long long)((rl >> 2) * 512 + c0 + (rl & 3)) * HH;
        int ko = (t & 7) * 4;
#pragma unroll
        for (int i = 0; i < 16; i++) {
            int k = ko + i * 32;
            float4 v = *(const float4*)(wp + k);
            ws[(k  )*16+rl]=v.x; ws[(k+1)*16+rl]=v.y;
            ws[(k+2)*16+rl]=v.z; ws[(k+3)*16+rl]=v.w;
        }
    }
    __syncthreads();
    {
        int r2 = (t & 7) * 2, b2 = (t >> 3) * 2;
        float a00=0.f,a01=0.f,a10=0.f,a11=0.f;
#pragma unroll 8
        for (int k = 0; k < 512; k++) {
            float2 hv = *(const float2*)&hs[k*32 + b2];
            float2 wv = *(const float2*)&ws[k*16 + r2];
            a00 += hv.x*wv.x; a01 += hv.x*wv.y;
            a10 += hv.y*wv.x; a11 += hv.y*wv.y;
        }
        gs[r2  ][b2]=a00; gs[r2+1][b2]=a01;
        gs[r2  ][b2+1]=a10; gs[r2+1][b2+1]=a11;
    }
    __syncthreads();
    {
        int b = t & 31, j = t >> 5;
        int col = c0 + j;
        const float* xw = g_xw + ((long long)cell * BB + b) * G4;
        float iv = gs[0*4+j][b] + xw[          col];
        float fv = gs[1*4+j][b] + xw[  512 +   col];
        float gv = gs[2*4+j][b] + xw[2*512 +   col];
        float ov = gs[3*4+j][b] + xw[3*512 +   col];
        float si = 1.f/(1.f+expf(-iv)), sf = 1.f/(1.f+expf(-fv));
        float so = 1.f/(1.f+expf(-ov)), tg = tanhf(gv);
        int ci = b * HH + col;
        float cold = g_cbuf[ci];
        float cn = sf * cold + si * tg;
        float hn = so * tanhf(cn);
        bool act = (cell == 0) || (g_declen[b] > (cell - 1));
        g_cbuf[ci] = act ? cn : cold;
        g_hbuf[(cell + 1) & 1][ci] = act ? hn : hprev[ci];
        if (cell >= 1)
            g_h2[((long long)(cell - 1) * BB + b) * HH + col] = hn;
    }
}

// ---- k6: predictions = mask( H2(1632x512) @ fc_w.T + fc_b ) via TF32 wmma
__global__ __launch_bounds__(256) void k6_fc(const float* __restrict__ fcw,
                                             const float* __restrict__ fcb,
                                             float* __restrict__ out, long long out_size) {
    __shared__ float sm[8448];
    float* As = sm;            // 64 x 36
    float* Bs = sm + 64*36;    // 128 x 36 (col-major [n][k])
    int t = threadIdx.x;
    int wid = t >> 5, wm = wid >> 2, wn = wid & 3;
    int m0 = blockIdx.x * 64, n0 = blockIdx.y * 128;
    const int M = TT * BB;

    const float* arp[2];
#pragma unroll
    for (int i = 0; i < 2; i++) {
        int r = m0 + ((t + i*256) >> 3);
        if (r >= M) r = 0;
        arp[i] = g_h2 + (long long)r * HH;
    }
    const float* brp[4];
#pragma unroll
    for (int i = 0; i < 4; i++) {
        int n = n0 + ((t + i*256) >> 3);
        if (n >= VV) n = VV - 1;
        brp[i] = fcw + (long long)n * HH;
    }

    wmma::fragment<wmma::accumulator,16,16,8,float> acc[2][2];
#pragma unroll
    for (int mi = 0; mi < 2; mi++)
#pragma unroll
        for (int nj = 0; nj < 2; nj++) wmma::fill_fragment(acc[mi][nj], 0.f);

    for (int k0 = 0; k0 < HH; k0 += 32) {
#pragma unroll
        for (int i = 0; i < 2; i++) {
            int idx = t + i*256, row = idx >> 3, q = idx & 7;
            *(float4*)&As[row*36 + q*4] = *(const float4*)(arp[i] + k0 + q*4);
        }
#pragma unroll
        for (int i = 0; i < 4; i++) {
            int idx = t + i*256, n = idx >> 3, q = idx & 7;
            *(float4*)&Bs[n*36 + q*4] = *(const float4*)(brp[i] + k0 + q*4);
        }
        __syncthreads();
#pragma unroll
        for (int ks = 0; ks < 4; ks++) {
            wmma::fragment<wmma::matrix_a,16,16,8,wmma::precision::tf32,wmma::row_major> af[2];
            wmma::fragment<wmma::matrix_b,16,16,8,wmma::precision::tf32,wmma::col_major> bf[2];
#pragma unroll
            for (int mi = 0; mi < 2; mi++) {
                wmma::load_matrix_sync(af[mi], &As[(wm*32 + mi*16)*36 + ks*8], 36);
#pragma unroll
                for (int e = 0; e < af[mi].num_elements; e++)
                    af[mi].x[e] = wmma::__float_to_tf32(af[mi].x[e]);
            }
#pragma unroll
            for (int nj = 0; nj < 2; nj++) {
                wmma::load_matrix_sync(bf[nj], &Bs[(wn*32 + nj*16)*36 + ks*8], 36);
#pragma unroll
                for (int e = 0; e < bf[nj].num_elements; e++)
                    bf[nj].x[e] = wmma::__float_to_tf32(bf[nj].x[e]);
            }
#pragma unroll
            for (int mi = 0; mi < 2; mi++)
#pragma unroll
                for (int nj = 0; nj < 2; nj++)
                    wmma::mma_sync(acc[mi][nj], af[mi], bf[nj], acc[mi][nj]);
        }
        __syncthreads();
    }
    float* sC = sm;   // 64 x 132
#pragma unroll
    for (int mi = 0; mi < 2; mi++)
#pragma unroll
        for (int nj = 0; nj < 2; nj++)
            wmma::store_matrix_sync(&sC[(wm*32 + mi*16)*132 + wn*32 + nj*16],
                                    acc[mi][nj], 132, wmma::mem_row_major);
    __syncthreads();
#pragma unroll
    for (int j = 0; j < 32; j++) {
        int e = t + j*256;
        int row = e >> 7, cl = e & 127;
        int rr = m0 + row;
        if (rr >= M) continue;
        int col = n0 + cl;
        if (col >= VV) continue;
        int tt = rr >> 5, bb = rr & 31;
        bool act = g_declen[bb] > tt;
        long long idx = (long long)bb * TT * VV + (long long)tt * VV + col;
        if (idx < out_size)
            out[idx] = act ? (sC[row*132 + cl] + fcb[col]) : 0.f;
    }
}

extern "C" void kernel_launch(void* const* d_in, const int* in_sizes, int n_in,
                              void* d_out, int out_size) {
    const float* enc   = (const float*)d_in[0];
    const int*   caps  = (const int*)  d_in[1];
    const int*   lens  = (const int*)  d_in[2];
    const float* embw  = (const float*)d_in[3];
    const float* initw = (const float*)d_in[4];
    const float* initb = (const float*)d_in[5];
    const float* gamma = (const float*)d_in[6];
    const float* beta  = (const float*)d_in[7];
    const float* wih   = (const float*)d_in[8];
    const float* whh   = (const float*)d_in[9];
    const float* bih   = (const float*)d_in[10];
    const float* bhh   = (const float*)d_in[11];
    const float* fcw   = (const float*)d_in[12];
    const float* fcb   = (const float*)d_in[13];
    float* out = (float*)d_out;
    long long osz = (long long)out_size;

    cudaFuncSetAttribute(k5_step, cudaFuncAttributeMaxDynamicSharedMemorySize, 98304);

    k0_setup<<<1, 256>>>(caps, lens, out, osz);
    k1_initgemm<<<KSPLIT, 256>>>(enc, initw);
    k2_bn<<<512, 128>>>(initb, gamma, beta);
    k4_xw<<<dim3(26, 16), 256>>>(embw, wih, bih, bhh);
    for (int cell = 0; cell < LL; cell++)
        k5_step<<<128, 128, 98304>>>(whh, cell);
    k6_fc<<<dim3(26, 79), 256>>>(fcw, fcb, out, osz);
}

// round 6
// speedup vs baseline: 1.4087x; 1.3501x over previous
#include <cuda_runtime.h>
#include <mma.h>
#include <math.h>

using namespace nvcuda;

#define BB 32
#define LL 52
#define VV 10000
#define HH 512
#define ENCK 401408
#define TT 51
#define G4 2048
#define KSPLIT 98
#define KCHUNK 4096

__device__ int   g_sort[BB];
__device__ int   g_declen[BB];
__device__ int   g_caps[BB*LL];
__device__ float g_part[(long long)KSPLIT*BB*HH];
__device__ float g_x0bn[BB*HH];
__device__ float g_xw[(long long)LL*BB*G4];
__device__ float g_hbuf[2][BB*HH];
__device__ float g_h2[(long long)TT*BB*HH];
__device__ unsigned g_bar;

// ---- cp.async helpers ----
__device__ __forceinline__ void cpa(void* s, const void* g) {
    unsigned sa = (unsigned)__cvta_generic_to_shared(s);
    asm volatile("cp.async.cg.shared.global [%0], [%1], 16;" :: "r"(sa), "l"(g));
}
__device__ __forceinline__ void cpc() { asm volatile("cp.async.commit_group;"); }
template<int N> __device__ __forceinline__ void cpw() {
    asm volatile("cp.async.wait_group %0;" :: "n"(N));
}

__global__ void k0_setup(const int* __restrict__ caps, const int* __restrict__ lens,
                         float* __restrict__ out, long long out_size) {
    int t = threadIdx.x;
    if (t == 0) {
        g_bar = 0u;
        int len[BB]; bool used[BB];
        for (int i = 0; i < BB; i++) { len[i] = lens[i]; used[i] = false; }
        for (int r = 0; r < BB; r++) {
            int best = -1;
            for (int i = 0; i < BB; i++)
                if (!used[i] && (best < 0 || len[i] > len[best])) best = i;
            used[best] = true; g_sort[r] = best; g_declen[r] = len[best] - 1;
        }
    }
    __syncthreads();
    long long P = (long long)BB * TT * VV;
    for (int i = t; i < BB*LL; i += blockDim.x) {
        int b = i / LL, c = i % LL;
        int v = caps[g_sort[b]*LL + c];
        g_caps[i] = v;
        if (P + i < out_size) out[P + i] = (float)v;
    }
    for (int i = t; i < BB; i += blockDim.x) {
        if (P + BB*LL + i      < out_size) out[P + BB*LL + i]      = (float)g_declen[i];
        if (P + BB*LL + BB + i < out_size) out[P + BB*LL + BB + i] = (float)g_sort[i];
    }
}

// ---- k1: x0 partials via TF32 wmma, double-buffered cp.async.
// grid KSPLIT=98 blocks; block covers all N=512; KCHUNK=4096 exact (no guards).
__global__ __launch_bounds__(256) void k1_initgemm(const float* __restrict__ enc,
                                                   const float* __restrict__ w) {
    extern __shared__ float sm1[];
    float* As[2] = { sm1, sm1 + 32*20 };                 // 32 x 20
    float* Bs[2] = { sm1 + 2*32*20, sm1 + 2*32*20 + 512*20 };  // 512 x 20
    int t = threadIdx.x;
    int wid = t >> 5;
    int kbase = blockIdx.x * KCHUNK;

    const float* arow = (t < 128) ? enc + (long long)g_sort[t >> 2] * ENCK : 0;
    int aq = t & 3;
    const float* brow[8];
#pragma unroll
    for (int i = 0; i < 8; i++) brow[i] = w + (long long)((t + i*256) >> 2) * ENCK;
    int bq = t & 3;

    wmma::fragment<wmma::accumulator,16,16,8,float> acc[2][4];
#pragma unroll
    for (int mi = 0; mi < 2; mi++)
#pragma unroll
        for (int nj = 0; nj < 4; nj++) wmma::fill_fragment(acc[mi][nj], 0.f);

    const int ITER = KCHUNK / 16;   // 256
    // prologue
    {
        int k0 = kbase;
        if (t < 128) cpa(&As[0][(t>>2)*20 + aq*4], arow + k0 + aq*4);
#pragma unroll
        for (int i = 0; i < 8; i++)
            cpa(&Bs[0][((t + i*256) >> 2)*20 + bq*4], brow[i] + k0 + bq*4);
        cpc();
    }
    for (int it = 0; it < ITER; it++) {
        int cur = it & 1, nxt = cur ^ 1;
        if (it + 1 < ITER) {
            int k0 = kbase + (it + 1) * 16;
            if (t < 128) cpa(&As[nxt][(t>>2)*20 + aq*4], arow + k0 + aq*4);
#pragma unroll
            for (int i = 0; i < 8; i++)
                cpa(&Bs[nxt][((t + i*256) >> 2)*20 + bq*4], brow[i] + k0 + bq*4);
            cpc();
            cpw<1>();
        } else cpw<0>();
        __syncthreads();
#pragma unroll
        for (int ks = 0; ks < 2; ks++) {
            wmma::fragment<wmma::matrix_a,16,16,8,wmma::precision::tf32,wmma::row_major> af[2];
            wmma::fragment<wmma::matrix_b,16,16,8,wmma::precision::tf32,wmma::col_major> bf[4];
#pragma unroll
            for (int mi = 0; mi < 2; mi++) {
                wmma::load_matrix_sync(af[mi], &As[cur][(mi*16)*20 + ks*8], 20);
#pragma unroll
                for (int e = 0; e < af[mi].num_elements; e++)
                    af[mi].x[e] = wmma::__float_to_tf32(af[mi].x[e]);
            }
#pragma unroll
            for (int nj = 0; nj < 4; nj++) {
                wmma::load_matrix_sync(bf[nj], &Bs[cur][(wid*64 + nj*16)*20 + ks*8], 20);
#pragma unroll
                for (int e = 0; e < bf[nj].num_elements; e++)
                    bf[nj].x[e] = wmma::__float_to_tf32(bf[nj].x[e]);
            }
#pragma unroll
            for (int mi = 0; mi < 2; mi++)
#pragma unroll
                for (int nj = 0; nj < 4; nj++)
                    wmma::mma_sync(acc[mi][nj], af[mi], bf[nj], acc[mi][nj]);
        }
        __syncthreads();
    }
    float* base = g_part + (long long)blockIdx.x * BB * HH;
#pragma unroll
    for (int mi = 0; mi < 2; mi++)
#pragma unroll
        for (int nj = 0; nj < 4; nj++)
            wmma::store_matrix_sync(base + mi*16*HH + wid*64 + nj*16,
                                    acc[mi][nj], HH, wmma::mem_row_major);
}

// reduce partials + bias + batchnorm(batch axis, 32)
__global__ void k2_bn(const float* __restrict__ bias, const float* __restrict__ gamma,
                      const float* __restrict__ beta) {
    int n = blockIdx.x, t = threadIdx.x;
    int b = t & 31, grp = t >> 5;
    float s = 0.f;
    for (int ks = grp; ks < KSPLIT; ks += 4)
        s += g_part[((long long)ks * BB + b) * HH + n];
    __shared__ float red[128];
    red[t] = s; __syncthreads();
    if (t < 32) {
        float x = red[t] + red[t+32] + red[t+64] + red[t+96] + bias[n];
        float sum = x, sq = x * x;
#pragma unroll
        for (int o = 16; o > 0; o >>= 1) {
            sum += __shfl_xor_sync(0xffffffffu, sum, o);
            sq  += __shfl_xor_sync(0xffffffffu, sq,  o);
        }
        float mu = sum * (1.f/32.f);
        float var = sq * (1.f/32.f) - mu * mu;
        g_x0bn[b * HH + n] = (x - mu) * rsqrtf(var + 1e-5f) * gamma[n] + beta[n];
    }
}

// ---- shared GEMM body for k4/k6: 64m x 128n block tile, TF32, double-buffered.
// As 64x36, Bs 128x36 per stage.
template<typename EPI>
__device__ __forceinline__ void gemm64x128(const float* const (&arp)[2],
                                           const float* const (&brp)[4],
                                           float* smbase, EPI epi) {
    float* As[2] = { smbase, smbase + 64*36 };
    float* Bs[2] = { smbase + 2*64*36, smbase + 2*64*36 + 128*36 };
    int t = threadIdx.x;
    int wid = t >> 5, wm = wid >> 2, wn = wid & 3;

    wmma::fragment<wmma::accumulator,16,16,8,float> acc[2][2];
#pragma unroll
    for (int mi = 0; mi < 2; mi++)
#pragma unroll
        for (int nj = 0; nj < 2; nj++) wmma::fill_fragment(acc[mi][nj], 0.f);

    const int ITER = HH / 32;   // 16
    {
#pragma unroll
        for (int i = 0; i < 2; i++) {
            int idx = t + i*256, row = idx >> 3, q = idx & 7;
            cpa(&As[0][row*36 + q*4], arp[i] + q*4);
        }
#pragma unroll
        for (int i = 0; i < 4; i++) {
            int idx = t + i*256, n = idx >> 3, q = idx & 7;
            cpa(&Bs[0][n*36 + q*4], brp[i] + q*4);
        }
        cpc();
    }
    for (int it = 0; it < ITER; it++) {
        int cur = it & 1, nxt = cur ^ 1;
        if (it + 1 < ITER) {
            int k0 = (it + 1) * 32;
#pragma unroll
            for (int i = 0; i < 2; i++) {
                int idx = t + i*256, row = idx >> 3, q = idx & 7;
                cpa(&As[nxt][row*36 + q*4], arp[i] + k0 + q*4);
            }
#pragma unroll
            for (int i = 0; i < 4; i++) {
                int idx = t + i*256, n = idx >> 3, q = idx & 7;
                cpa(&Bs[nxt][n*36 + q*4], brp[i] + k0 + q*4);
            }
            cpc();
            cpw<1>();
        } else cpw<0>();
        __syncthreads();
#pragma unroll
        for (int ks = 0; ks < 4; ks++) {
            wmma::fragment<wmma::matrix_a,16,16,8,wmma::precision::tf32,wmma::row_major> af[2];
            wmma::fragment<wmma::matrix_b,16,16,8,wmma::precision::tf32,wmma::col_major> bf[2];
#pragma unroll
            for (int mi = 0; mi < 2; mi++) {
                wmma::load_matrix_sync(af[mi], &As[cur][(wm*32 + mi*16)*36 + ks*8], 36);
#pragma unroll
                for (int e = 0; e < af[mi].num_elements; e++)
                    af[mi].x[e] = wmma::__float_to_tf32(af[mi].x[e]);
            }
#pragma unroll
            for (int nj = 0; nj < 2; nj++) {
                wmma::load_matrix_sync(bf[nj], &Bs[cur][(wn*32 + nj*16)*36 + ks*8], 36);
#pragma unroll
                for (int e = 0; e < bf[nj].num_elements; e++)
                    bf[nj].x[e] = wmma::__float_to_tf32(bf[nj].x[e]);
            }
#pragma unroll
            for (int mi = 0; mi < 2; mi++)
#pragma unroll
                for (int nj = 0; nj < 2; nj++)
                    wmma::mma_sync(acc[mi][nj], af[mi], bf[nj], acc[mi][nj]);
        }
        __syncthreads();
    }
    float* sC = smbase;   // 64 x 132
#pragma unroll
    for (int mi = 0; mi < 2; mi++)
#pragma unroll
        for (int nj = 0; nj < 2; nj++)
            wmma::store_matrix_sync(&sC[(wm*32 + mi*16)*132 + wn*32 + nj*16],
                                    acc[mi][nj], 132, wmma::mem_row_major);
    __syncthreads();
    epi(sC);
}

// ---- k4: XW = [x0_bn; emb](1664x512) @ w_ih.T + bias
__global__ __launch_bounds__(256) void k4_xw(const float* __restrict__ embw,
                                             const float* __restrict__ wih,
                                             const float* __restrict__ bih,
                                             const float* __restrict__ bhh) {
    extern __shared__ float sm4[];
    int t = threadIdx.x;
    int m0 = blockIdx.x * 64, n0 = blockIdx.y * 128;
    const float* arp[2];
#pragma unroll
    for (int i = 0; i < 2; i++) {
        int r = m0 + ((t + i*256) >> 3);
        if (r < BB) arp[i] = g_x0bn + r * HH;
        else { int rr = r - BB; arp[i] = embw + (long long)g_caps[(rr & 31)*LL + (rr >> 5)] * HH; }
    }
    const float* brp[4];
#pragma unroll
    for (int i = 0; i < 4; i++)
        brp[i] = wih + (long long)(n0 + ((t + i*256) >> 3)) * HH;

    gemm64x128(arp, brp, sm4, [&](float* sC) {
#pragma unroll
        for (int j = 0; j < 32; j++) {
            int e = t + j*256;
            int row = e >> 7, cl = e & 127;
            int col = n0 + cl;
            g_xw[(long long)(m0 + row) * G4 + col] = sC[row*132 + cl] + bih[col] + bhh[col];
        }
    });
}

// ---- k5: persistent LSTM, all 52 cells in one kernel, grid 128 blocks (all resident).
__global__ __launch_bounds__(128) void k5_all(const float* __restrict__ whh) {
    extern __shared__ float dyn[];
    float* hs = dyn;              // [512][32]
    float* ws = dyn + 512 * 32;   // [512][16]
    __shared__ float gs[16][33];
    int t = threadIdx.x;
    int c0 = blockIdx.x * 4;

    {   // load 16 w_hh rows ONCE: rl = g*4+j  <->  R = g*512 + c0 + j
        int rl = t >> 3;
        const float* wp = whh + (long long)((rl >> 2) * 512 + c0 + (rl & 3)) * HH;
        int ko = (t & 7) * 4;
#pragma unroll
        for (int i = 0; i < 16; i++) {
            int k = ko + i * 32;
            float4 v = *(const float4*)(wp + k);
            ws[(k  )*16+rl]=v.x; ws[(k+1)*16+rl]=v.y;
            ws[(k+2)*16+rl]=v.z; ws[(k+3)*16+rl]=v.w;
        }
    }

    // per-thread owned cell state (elementwise mapping: b = t&31, j = t>>5)
    int eb = t & 31, ej = t >> 5;
    int ecol = c0 + ej;
    float c_reg = 0.f, h_reg = 0.f;
    int dl = g_declen[eb];

    int lb = t >> 2, ko2 = (t & 3) * 4;     // hs load mapping
    int r2 = (t & 7) * 2, b2 = (t >> 3) * 2;  // dot mapping

    for (int cell = 0; cell < LL; cell++) {
        if (cell == 0) {
            for (int i = t; i < 512*32; i += 128) hs[i] = 0.f;
        } else {
            const float* hp = g_hbuf[cell & 1] + lb * HH;
#pragma unroll
            for (int i = 0; i < 32; i++) {
                int k = ko2 + i * 16;
                float4 v = __ldcg((const float4*)(hp + k));
                hs[(k  )*32+lb]=v.x; hs[(k+1)*32+lb]=v.y;
                hs[(k+2)*32+lb]=v.z; hs[(k+3)*32+lb]=v.w;
            }
        }
        __syncthreads();
        {   // dots: thread = 2b x 2r
            float a00=0.f,a01=0.f,a10=0.f,a11=0.f;
#pragma unroll 8
            for (int k = 0; k < 512; k++) {
                float2 hv = *(const float2*)&hs[k*32 + b2];
                float2 wv = *(const float2*)&ws[k*16 + r2];
                a00 += hv.x*wv.x; a01 += hv.x*wv.y;
                a10 += hv.y*wv.x; a11 += hv.y*wv.y;
            }
            gs[r2  ][b2]=a00; gs[r2+1][b2]=a01;
            gs[r2  ][b2+1]=a10; gs[r2+1][b2+1]=a11;
        }
        __syncthreads();
        {   // elementwise (state in registers)
            const float* xw = g_xw + ((long long)cell * BB + eb) * G4;
            float iv = gs[0*4+ej][eb] + xw[          ecol];
            float fv = gs[1*4+ej][eb] + xw[  512 +   ecol];
            float gv = gs[2*4+ej][eb] + xw[2*512 +   ecol];
            float ov = gs[3*4+ej][eb] + xw[3*512 +   ecol];
            float si = 1.f/(1.f+expf(-iv)), sf = 1.f/(1.f+expf(-fv));
            float so = 1.f/(1.f+expf(-ov)), tg = tanhf(gv);
            float cn = sf * c_reg + si * tg;
            float hn = so * tanhf(cn);
            bool act = (cell == 0) || (dl > (cell - 1));
            c_reg = act ? cn : c_reg;
            h_reg = act ? hn : h_reg;
            int ci = eb * HH + ecol;
            g_hbuf[(cell + 1) & 1][ci] = h_reg;
            if (cell >= 1)
                g_h2[((long long)(cell - 1) * BB + eb) * HH + ecol] = hn;
        }
        __syncthreads();
        if (cell + 1 < LL) {   // grid barrier
            if (t == 0) {
                __threadfence();
                atomicAdd(&g_bar, 1u);
                unsigned tgt = (unsigned)(cell + 1) * gridDim.x;
                while (*(volatile unsigned*)&g_bar < tgt) __nanosleep(64);
            }
            __syncthreads();
        }
    }
}

// ---- k6: predictions = mask( H2(1632x512) @ fc_w.T + fc_b )
__global__ __launch_bounds__(256) void k6_fc(const float* __restrict__ fcw,
                                             const float* __restrict__ fcb,
                                             float* __restrict__ out, long long out_size) {
    extern __shared__ float sm6[];
    int t = threadIdx.x;
    int m0 = blockIdx.x * 64, n0 = blockIdx.y * 128;
    const int M = TT * BB;
    const float* arp[2];
#pragma unroll
    for (int i = 0; i < 2; i++) {
        int r = m0 + ((t + i*256) >> 3);
        if (r >= M) r = 0;
        arp[i] = g_h2 + (long long)r * HH;
    }
    const float* brp[4];
#pragma unroll
    for (int i = 0; i < 4; i++) {
        int n = n0 + ((t + i*256) >> 3);
        if (n >= VV) n = VV - 1;
        brp[i] = fcw + (long long)n * HH;
    }
    gemm64x128(arp, brp, sm6, [&](float* sC) {
#pragma unroll
        for (int j = 0; j < 32; j++) {
            int e = t + j*256;
            int row = e >> 7, cl = e & 127;
            int rr = m0 + row;
            if (rr >= M) continue;
            int col = n0 + cl;
            if (col >= VV) continue;
            int tt = rr >> 5, bb = rr & 31;
            bool act = g_declen[bb] > tt;
            long long idx = (long long)bb * TT * VV + (long long)tt * VV + col;
            if (idx < out_size)
                out[idx] = act ? (sC[row*132 + cl] + fcb[col]) : 0.f;
        }
    });
}

extern "C" void kernel_launch(void* const* d_in, const int* in_sizes, int n_in,
                              void* d_out, int out_size) {
    const float* enc   = (const float*)d_in[0];
    const int*   caps  = (const int*)  d_in[1];
    const int*   lens  = (const int*)  d_in[2];
    const float* embw  = (const float*)d_in[3];
    const float* initw = (const float*)d_in[4];
    const float* initb = (const float*)d_in[5];
    const float* gamma = (const float*)d_in[6];
    const float* beta  = (const float*)d_in[7];
    const float* wih   = (const float*)d_in[8];
    const float* whh   = (const float*)d_in[9];
    const float* bih   = (const float*)d_in[10];
    const float* bhh   = (const float*)d_in[11];
    const float* fcw   = (const float*)d_in[12];
    const float* fcb   = (const float*)d_in[13];
    float* out = (float*)d_out;
    long long osz = (long long)out_size;

    const int SM1 = (2*32*20 + 2*512*20) * 4;       // 87,040 B
    const int SMG = (2*64*36 + 2*128*36) * 4;       // 55,296 B
    const int SM5 = (512*32 + 512*16) * 4;          // 98,304 B
    cudaFuncSetAttribute(k1_initgemm, cudaFuncAttributeMaxDynamicSharedMemorySize, SM1);
    cudaFuncSetAttribute(k4_xw,       cudaFuncAttributeMaxDynamicSharedMemorySize, SMG);
    cudaFuncSetAttribute(k6_fc,       cudaFuncAttributeMaxDynamicSharedMemorySize, SMG);
    cudaFuncSetAttribute(k5_all,      cudaFuncAttributeMaxDynamicSharedMemorySize, SM5);

    k0_setup<<<1, 256>>>(caps, lens, out, osz);
    k1_initgemm<<<KSPLIT, 256, SM1>>>(enc, initw);
    k2_bn<<<512, 128>>>(initb, gamma, beta);
    k4_xw<<<dim3(26, 16), 256, SMG>>>(embw, wih, bih, bhh);
    k5_all<<<128, 128, SM5>>>(whh);
    k6_fc<<<dim3(26, 79), 256, SMG>>>(fcw, fcb, out, osz);
}

// round 7
// speedup vs baseline: 1.4386x; 1.0213x over previous
#include <cuda_runtime.h>
#include <mma.h>
#include <math.h>

using namespace nvcuda;

#define BB 32
#define LL 52
#define VV 10000
#define HH 512
#define ENCK 401408
#define TT 51
#define G4 2048
#define KSPLIT 32
#define KCHUNK 12544   /* 32 * 12544 = 401408 exact */

__device__ int   g_sort[BB];
__device__ int   g_declen[BB];
__device__ int   g_caps[BB*LL];
__device__ float g_part[(long long)KSPLIT*BB*HH];
__device__ float g_x0bn[BB*HH];
__device__ float g_xw[(long long)LL*BB*G4];
__device__ float g_hbuf[2][BB*HH];
__device__ float g_h2[(long long)TT*BB*HH];
__device__ unsigned g_bar;

// ---------------- TMA 1D bulk + mbarrier helpers ----------------
__device__ __forceinline__ unsigned smaddr(const void* p) {
    return (unsigned)__cvta_generic_to_shared(p);
}
__device__ __forceinline__ void mbinit(unsigned mbar, unsigned cnt) {
    asm volatile("mbarrier.init.shared.b64 [%0], %1;" :: "r"(mbar), "r"(cnt) : "memory");
}
__device__ __forceinline__ void mexpect(unsigned mbar, unsigned bytes) {
    asm volatile("mbarrier.arrive.expect_tx.shared.b64 _, [%0], %1;"
                 :: "r"(mbar), "r"(bytes) : "memory");
}
__device__ __forceinline__ void mwait(unsigned mbar, unsigned parity) {
    asm volatile(
        "{\n\t.reg .pred P;\n\t"
        "LW%=:\n\t"
        "mbarrier.try_wait.parity.acquire.cta.shared::cta.b64 P, [%0], %1, 0x989680;\n\t"
        "@P bra LD%=;\n\t"
        "bra LW%=;\n\t"
        "LD%=:\n\t}"
        :: "r"(mbar), "r"(parity) : "memory");
}
__device__ __forceinline__ void bulkcp(unsigned dst, const void* src, unsigned bytes, unsigned mbar) {
    asm volatile(
        "cp.async.bulk.shared::cluster.global.mbarrier::complete_tx::bytes [%0], [%1], %2, [%3];"
        :: "r"(dst), "l"(src), "r"(bytes), "r"(mbar) : "memory");
}

__global__ void k0_setup(const int* __restrict__ caps, const int* __restrict__ lens,
                         float* __restrict__ out, long long out_size) {
    int t = threadIdx.x;
    if (t == 0) {
        g_bar = 0u;
        int len[BB]; bool used[BB];
        for (int i = 0; i < BB; i++) { len[i] = lens[i]; used[i] = false; }
        for (int r = 0; r < BB; r++) {
            int best = -1;
            for (int i = 0; i < BB; i++)
                if (!used[i] && (best < 0 || len[i] > len[best])) best = i;
            used[best] = true; g_sort[r] = best; g_declen[r] = len[best] - 1;
        }
    }
    __syncthreads();
    long long P = (long long)BB * TT * VV;
    for (int i = t; i < BB*LL; i += blockDim.x) {
        int b = i / LL, c = i % LL;
        int v = caps[g_sort[b]*LL + c];
        g_caps[i] = v;
        if (P + i < out_size) out[P + i] = (float)v;
    }
    for (int i = t; i < BB; i += blockDim.x) {
        if (P + BB*LL + i      < out_size) out[P + BB*LL + i]      = (float)g_declen[i];
        if (P + BB*LL + BB + i < out_size) out[P + BB*LL + BB + i] = (float)g_sort[i];
    }
}

// ---- k1: x0 partials. Tile 32m x 128n, K-split 32, stage K=128 (512B bulk rows).
// grid (4 n-tiles, 32 ksplit), 256 thr. smem: 2 stages x (32+128) rows x 132 floats.
__global__ __launch_bounds__(256) void k1_initgemm(const float* __restrict__ enc,
                                                   const float* __restrict__ w) {
    extern __shared__ float sm[];
    __shared__ unsigned long long mb[2];
    int t = threadIdx.x;
    int wid = t >> 5;
    int n0 = blockIdx.x * 128;
    long long kbase = (long long)blockIdx.y * KCHUNK;
    unsigned mbar[2] = { smaddr(&mb[0]), smaddr(&mb[1]) };
    if (t == 0) { mbinit(mbar[0], 1); mbinit(mbar[1], 1); }
    __syncthreads();

    const int STAGES = KCHUNK / 128;        // 98
    const unsigned STB = 160u * 512u;       // 81920 bytes/stage
    const int SST = 160 * 132;              // stage stride in floats

    // per-thread copy role: t<128 -> B row t; t in [128,160) -> A row t-128
    const float* src0 = 0;
    int drow = 0;
    if (t < 128) { src0 = w + (long long)(n0 + t) * ENCK + kbase; drow = (32 + t) * 132; }
    else if (t < 160) { src0 = enc + (long long)g_sort[t-128] * ENCK + kbase; drow = (t - 128) * 132; }

    wmma::fragment<wmma::accumulator,16,16,8,float> acc[2];
    wmma::fill_fragment(acc[0], 0.f);
    wmma::fill_fragment(acc[1], 0.f);

    // prologue: stages 0,1
    if (t == 0) mexpect(mbar[0], STB);
    __syncthreads();
    if (t < 160) bulkcp(smaddr(sm + drow), src0, 512, mbar[0]);
    if (t == 0) mexpect(mbar[1], STB);
    __syncthreads();
    if (t < 160) bulkcp(smaddr(sm + SST + drow), src0 + 128, 512, mbar[1]);

    for (int s = 0; s < STAGES; s++) {
        int c = s & 1;
        mwait(mbar[c], (unsigned)((s >> 1) & 1));
        float* As = sm + c * SST;
        float* Bs = As + 32 * 132;
#pragma unroll
        for (int ks = 0; ks < 16; ks++) {
            wmma::fragment<wmma::matrix_a,16,16,8,wmma::precision::tf32,wmma::row_major> af[2];
            wmma::fragment<wmma::matrix_b,16,16,8,wmma::precision::tf32,wmma::col_major> bf;
#pragma unroll
            for (int mi = 0; mi < 2; mi++) {
                wmma::load_matrix_sync(af[mi], &As[(mi*16)*132 + ks*8], 132);
#pragma unroll
                for (int e = 0; e < af[mi].num_elements; e++)
                    af[mi].x[e] = wmma::__float_to_tf32(af[mi].x[e]);
            }
            wmma::load_matrix_sync(bf, &Bs[(wid*16)*132 + ks*8], 132);
#pragma unroll
            for (int e = 0; e < bf.num_elements; e++)
                bf.x[e] = wmma::__float_to_tf32(bf.x[e]);
            wmma::mma_sync(acc[0], af[0], bf, acc[0]);
            wmma::mma_sync(acc[1], af[1], bf, acc[1]);
        }
        __syncthreads();
        if (s + 2 < STAGES) {
            if (t == 0) mexpect(mbar[c], STB);
            __syncthreads();
            if (t < 160) bulkcp(smaddr(sm + c * SST + drow), src0 + (long long)(s+2)*128, 512, mbar[c]);
        }
    }
    float* base = g_part + (long long)blockIdx.y * BB * HH;
    wmma::store_matrix_sync(base +        n0 + wid*16, acc[0], HH, wmma::mem_row_major);
    wmma::store_matrix_sync(base + 16*HH + n0 + wid*16, acc[1], HH, wmma::mem_row_major);
}

// reduce partials + bias + batchnorm(batch axis, 32)
__global__ void k2_bn(const float* __restrict__ bias, const float* __restrict__ gamma,
                      const float* __restrict__ beta) {
    int n = blockIdx.x, t = threadIdx.x;
    int b = t & 31, grp = t >> 5;
    float s = 0.f;
    for (int ks = grp; ks < KSPLIT; ks += 4)
        s += g_part[((long long)ks * BB + b) * HH + n];
    __shared__ float red[128];
    red[t] = s; __syncthreads();
    if (t < 32) {
        float x = red[t] + red[t+32] + red[t+64] + red[t+96] + bias[n];
        float sum = x, sq = x * x;
#pragma unroll
        for (int o = 16; o > 0; o >>= 1) {
            sum += __shfl_xor_sync(0xffffffffu, sum, o);
            sq  += __shfl_xor_sync(0xffffffffu, sq,  o);
        }
        float mu = sum * (1.f/32.f);
        float var = sq * (1.f/32.f) - mu * mu;
        g_x0bn[b * HH + n] = (x - mu) * rsqrtf(var + 1e-5f) * gamma[n] + beta[n];
    }
}

// ---- shared bulk-TMA GEMM body: tile 128m x 256n, K=512, stage K=64 (256B rows).
// 8 warps, warp tile 64x64 (acc[4][4]). arow0: this thread's A row src (t<128), brow0: B row src.
template<typename EPI>
__device__ __forceinline__ void bulk_gemm(const float* arow0, const float* brow0,
                                          float* sm, EPI epi) {
    __shared__ unsigned long long mb[2];
    int t = threadIdx.x;
    int wid = t >> 5, wm = wid >> 2, wn = wid & 3;
    unsigned mbar[2] = { smaddr(&mb[0]), smaddr(&mb[1]) };
    if (t == 0) { mbinit(mbar[0], 1); mbinit(mbar[1], 1); }
    __syncthreads();

    const int STAGES = HH / 64;             // 8
    const unsigned STB = 384u * 256u;       // 98304 bytes/stage
    const int SST = 384 * 68;               // stage stride (floats)
    int adrow = t * 68;                     // A rows 0..127 at offset row*68
    int bdrow = (128 + t) * 68;             // B rows at offset (128+row)*68

    wmma::fragment<wmma::accumulator,16,16,8,float> acc[4][4];
#pragma unroll
    for (int mi = 0; mi < 4; mi++)
#pragma unroll
        for (int nj = 0; nj < 4; nj++) wmma::fill_fragment(acc[mi][nj], 0.f);

    if (t == 0) mexpect(mbar[0], STB);
    __syncthreads();
    bulkcp(smaddr(sm + bdrow), brow0, 256, mbar[0]);
    if (t < 128) bulkcp(smaddr(sm + adrow), arow0, 256, mbar[0]);
    if (t == 0) mexpect(mbar[1], STB);
    __syncthreads();
    bulkcp(smaddr(sm + SST + bdrow), brow0 + 64, 256, mbar[1]);
    if (t < 128) bulkcp(smaddr(sm + SST + adrow), arow0 + 64, 256, mbar[1]);

    for (int s = 0; s < STAGES; s++) {
        int c = s & 1;
        mwait(mbar[c], (unsigned)((s >> 1) & 1));
        float* As = sm + c * SST;
        float* Bs = As + 128 * 68;
#pragma unroll
        for (int ks = 0; ks < 8; ks++) {
            wmma::fragment<wmma::matrix_a,16,16,8,wmma::precision::tf32,wmma::row_major> af[4];
            wmma::fragment<wmma::matrix_b,16,16,8,wmma::precision::tf32,wmma::col_major> bf[4];
#pragma unroll
            for (int mi = 0; mi < 4; mi++) {
                wmma::load_matrix_sync(af[mi], &As[(wm*64 + mi*16)*68 + ks*8], 68);
#pragma unroll
                for (int e = 0; e < af[mi].num_elements; e++)
                    af[mi].x[e] = wmma::__float_to_tf32(af[mi].x[e]);
            }
#pragma unroll
            for (int nj = 0; nj < 4; nj++) {
                wmma::load_matrix_sync(bf[nj], &Bs[(wn*64 + nj*16)*68 + ks*8], 68);
#pragma unroll
                for (int e = 0; e < bf[nj].num_elements; e++)
                    bf[nj].x[e] = wmma::__float_to_tf32(bf[nj].x[e]);
            }
#pragma unroll
            for (int mi = 0; mi < 4; mi++)
#pragma unroll
                for (int nj = 0; nj < 4; nj++)
                    wmma::mma_sync(acc[mi][nj], af[mi], bf[nj], acc[mi][nj]);
        }
        __syncthreads();
        if (s + 2 < STAGES) {
            if (t == 0) mexpect(mbar[c], STB);
            __syncthreads();
            bulkcp(smaddr(sm + c*SST + bdrow), brow0 + (s+2)*64, 256, mbar[c]);
            if (t < 128) bulkcp(smaddr(sm + c*SST + adrow), arow0 + (s+2)*64, 256, mbar[c]);
        }
    }
    // epilogue: stage result in smem (128 x 260)
    float* sC = sm;
#pragma unroll
    for (int mi = 0; mi < 4; mi++)
#pragma unroll
        for (int nj = 0; nj < 4; nj++)
            wmma::store_matrix_sync(&sC[(wm*64 + mi*16)*260 + wn*64 + nj*16],
                                    acc[mi][nj], 260, wmma::mem_row_major);
    __syncthreads();
    epi(sC);
}

// ---- k4: XW = [x0_bn; emb](1664x512) @ w_ih.T + bias. grid (13, 8).
__global__ __launch_bounds__(256) void k4_xw(const float* __restrict__ embw,
                                             const float* __restrict__ wih,
                                             const float* __restrict__ bih,
                                             const float* __restrict__ bhh) {
    extern __shared__ float sm4[];
    int t = threadIdx.x;
    int m0 = blockIdx.x * 128, n0 = blockIdx.y * 256;
    const float* arow0 = 0;
    if (t < 128) {
        int r = m0 + t;
        if (r < BB) arow0 = g_x0bn + r * HH;
        else { int rr = r - BB; arow0 = embw + (long long)g_caps[(rr & 31)*LL + (rr >> 5)] * HH; }
    }
    const float* brow0 = wih + (long long)(n0 + t) * HH;
    bulk_gemm(arow0, brow0, sm4, [&](float* sC) {
#pragma unroll
        for (int j = 0; j < 128; j++) {
            int e = t + j*256;
            int row = e >> 8, cl = e & 255;
            int col = n0 + cl;
            g_xw[(long long)(m0 + row) * G4 + col] = sC[row*260 + cl] + bih[col] + bhh[col];
        }
    });
}

// ---- k5: persistent LSTM, all 52 cells, grid 128 blocks (all resident).
__global__ __launch_bounds__(128) void k5_all(const float* __restrict__ whh) {
    extern __shared__ float dyn[];
    float* hs = dyn;              // [512][32]
    float* ws = dyn + 512 * 32;   // [512][16]
    __shared__ float gs[16][33];
    int t = threadIdx.x;
    int c0 = blockIdx.x * 4;

    {   // load 16 w_hh rows ONCE
        int rl = t >> 3;
        const float* wp = whh + (long long)((rl >> 2) * 512 + c0 + (rl & 3)) * HH;
        int ko = (t & 7) * 4;
#pragma unroll
        for (int i = 0; i < 16; i++) {
            int k = ko + i * 32;
            float4 v = *(const float4*)(wp + k);
            ws[(k  )*16+rl]=v.x; ws[(k+1)*16+rl]=v.y;
            ws[(k+2)*16+rl]=v.z; ws[(k+3)*16+rl]=v.w;
        }
    }
    int eb = t & 31, ej = t >> 5;
    int ecol = c0 + ej;
    float c_reg = 0.f, h_reg = 0.f;
    int dl = g_declen[eb];
    int lb = t >> 2, ko2 = (t & 3) * 4;
    int r2 = (t & 7) * 2, b2 = (t >> 3) * 2;

    for (int cell = 0; cell < LL; cell++) {
        if (cell == 0) {
            for (int i = t; i < 512*32; i += 128) hs[i] = 0.f;
        } else {
            const float* hp = g_hbuf[cell & 1] + lb * HH;
#pragma unroll
            for (int i = 0; i < 32; i++) {
                int k = ko2 + i * 16;
                float4 v = __ldcg((const float4*)(hp + k));
                hs[(k  )*32+lb]=v.x; hs[(k+1)*32+lb]=v.y;
                hs[(k+2)*32+lb]=v.z; hs[(k+3)*32+lb]=v.w;
            }
        }
        __syncthreads();
        {
            float a00=0.f,a01=0.f,a10=0.f,a11=0.f;
#pragma unroll 8
            for (int k = 0; k < 512; k++) {
                float2 hv = *(const float2*)&hs[k*32 + b2];
                float2 wv = *(const float2*)&ws[k*16 + r2];
                a00 += hv.x*wv.x; a01 += hv.x*wv.y;
                a10 += hv.y*wv.x; a11 += hv.y*wv.y;
            }
            gs[r2  ][b2]=a00; gs[r2+1][b2]=a01;
            gs[r2  ][b2+1]=a10; gs[r2+1][b2+1]=a11;
        }
        __syncthreads();
        {
            const float* xw = g_xw + ((long long)cell * BB + eb) * G4;
            float iv = gs[0*4+ej][eb] + xw[          ecol];
            float fv = gs[1*4+ej][eb] + xw[  512 +   ecol];
            float gv = gs[2*4+ej][eb] + xw[2*512 +   ecol];
            float ov = gs[3*4+ej][eb] + xw[3*512 +   ecol];
            float si = 1.f/(1.f+expf(-iv)), sf = 1.f/(1.f+expf(-fv));
            float so = 1.f/(1.f+expf(-ov)), tg = tanhf(gv);
            float cn = sf * c_reg + si * tg;
            float hn = so * tanhf(cn);
            bool act = (cell == 0) || (dl > (cell - 1));
            c_reg = act ? cn : c_reg;
            h_reg = act ? hn : h_reg;
            int ci = eb * HH + ecol;
            g_hbuf[(cell + 1) & 1][ci] = h_reg;
            if (cell >= 1)
                g_h2[((long long)(cell - 1) * BB + eb) * HH + ecol] = hn;
        }
        __syncthreads();
        if (cell + 1 < LL) {
            if (t == 0) {
                __threadfence();
                atomicAdd(&g_bar, 1u);
                unsigned tgt = (unsigned)(cell + 1) * gridDim.x;
                while (*(volatile unsigned*)&g_bar < tgt) __nanosleep(64);
            }
            __syncthreads();
        }
    }
}

// ---- k6: predictions = mask( H2(1632x512) @ fc_w.T + fc_b ). grid (13, 40).
__global__ __launch_bounds__(256) void k6_fc(const float* __restrict__ fcw,
                                             const float* __restrict__ fcb,
                                             float* __restrict__ out, long long out_size) {
    extern __shared__ float sm6[];
    int t = threadIdx.x;
    int m0 = blockIdx.x * 128, n0 = blockIdx.y * 256;
    const int M = TT * BB;
    const float* arow0 = 0;
    if (t < 128) {
        int r = m0 + t;
        if (r >= M) r = 0;
        arow0 = g_h2 + (long long)r * HH;
    }
    int bn = n0 + t; if (bn >= VV) bn = VV - 1;
    const float* brow0 = fcw + (long long)bn * HH;
    bulk_gemm(arow0, brow0, sm6, [&](float* sC) {
#pragma unroll
        for (int j = 0; j < 128; j++) {
            int e = t + j*256;
            int row = e >> 8, cl = e & 255;
            int rr = m0 + row;
            if (rr >= M) continue;
            int col = n0 + cl;
            if (col >= VV) continue;
            int tt = rr >> 5, bb = rr & 31;
            bool act = g_declen[bb] > tt;
            long long idx = (long long)bb * TT * VV + (long long)tt * VV + col;
            if (idx < out_size)
                out[idx] = act ? (sC[row*260 + cl] + fcb[col]) : 0.f;
        }
    });
}

extern "C" void kernel_launch(void* const* d_in, const int* in_sizes, int n_in,
                              void* d_out, int out_size) {
    const float* enc   = (const float*)d_in[0];
    const int*   caps  = (const int*)  d_in[1];
    const int*   lens  = (const int*)  d_in[2];
    const float* embw  = (const float*)d_in[3];
    const float* initw = (const float*)d_in[4];
    const float* initb = (const float*)d_in[5];
    const float* gamma = (const float*)d_in[6];
    const float* beta  = (const float*)d_in[7];
    const float* wih   = (const float*)d_in[8];
    const float* whh   = (const float*)d_in[9];
    const float* bih   = (const float*)d_in[10];
    const float* bhh   = (const float*)d_in[11];
    const float* fcw   = (const float*)d_in[12];
    const float* fcb   = (const float*)d_in[13];
    float* out = (float*)d_out;
    long long osz = (long long)out_size;

    const int SM1 = 2 * 160 * 132 * 4;      // 168,960 B
    const int SMG = 2 * 384 * 68  * 4;      // 208,896 B
    const int SM5 = (512*32 + 512*16) * 4;  // 98,304 B
    cudaFuncSetAttribute(k1_initgemm, cudaFuncAttributeMaxDynamicSharedMemorySize, SM1);
    cudaFuncSetAttribute(k4_xw,       cudaFuncAttributeMaxDynamicSharedMemorySize, SMG);
    cudaFuncSetAttribute(k6_fc,       cudaFuncAttributeMaxDynamicSharedMemorySize, SMG);
    cudaFuncSetAttribute(k5_all,      cudaFuncAttributeMaxDynamicSharedMemorySize, SM5);

    k0_setup<<<1, 256>>>(caps, lens, out, osz);
    k1_initgemm<<<dim3(4, KSPLIT), 256, SM1>>>(enc, initw);
    k2_bn<<<512, 128>>>(initb, gamma, beta);
    k4_xw<<<dim3(13, 8), 256, SMG>>>(embw, wih, bih, bhh);
    k5_all<<<128, 128, SM5>>>(whh);
    k6_fc<<<dim3(13, 40), 256, SMG>>>(fcw, fcb, out, osz);
}

// round 8
// speedup vs baseline: 1.7325x; 1.2043x over previous
#include <cuda_runtime.h>
#include <cuda_fp16.h>
#include <mma.h>
#include <math.h>

using namespace nvcuda;

#define BB 32
#define LL 52
#define VV 10000
#define HH 512
#define ENCK 401408
#define TT 51
#define G4 2048
#define KSPLIT 32
#define KCHUNK 12544   /* 32 * 12544 = 401408 exact */
#define MROWS 1664     /* 32 + 51*32 */

__device__ int   g_sort[BB];
__device__ int   g_declen[BB];
__device__ int   g_caps[BB*LL];
__device__ float g_part[(long long)KSPLIT*BB*HH];
__device__ float g_x0bn[BB*HH];
__device__ float g_xw[(long long)LL*BB*G4];
__device__ float g_hbuf[2][BB*HH];
__device__ unsigned g_bar;
__device__ __half g_wih_h[(long long)G4*HH];
__device__ __half g_fcw_h[(long long)VV*HH];
__device__ __half g_a4h[(long long)MROWS*HH];
__device__ __half g_h2h[(long long)TT*BB*HH];

// ---------------- TMA 1D bulk + mbarrier helpers ----------------
__device__ __forceinline__ unsigned smaddr(const void* p) {
    return (unsigned)__cvta_generic_to_shared(p);
}
__device__ __forceinline__ void mbinit(unsigned mbar, unsigned cnt) {
    asm volatile("mbarrier.init.shared.b64 [%0], %1;" :: "r"(mbar), "r"(cnt) : "memory");
}
__device__ __forceinline__ void mexpect(unsigned mbar, unsigned bytes) {
    asm volatile("mbarrier.arrive.expect_tx.shared.b64 _, [%0], %1;"
                 :: "r"(mbar), "r"(bytes) : "memory");
}
__device__ __forceinline__ void mwait(unsigned mbar, unsigned parity) {
    asm volatile(
        "{\n\t.reg .pred P;\n\t"
        "LW%=:\n\t"
        "mbarrier.try_wait.parity.acquire.cta.shared::cta.b64 P, [%0], %1, 0x989680;\n\t"
        "@P bra LD%=;\n\t"
        "bra LW%=;\n\t"
        "LD%=:\n\t}"
        :: "r"(mbar), "r"(parity) : "memory");
}
__device__ __forceinline__ void bulkcp(unsigned dst, const void* src, unsigned bytes, unsigned mbar) {
    asm volatile(
        "cp.async.bulk.shared::cluster.global.mbarrier::complete_tx::bytes [%0], [%1], %2, [%3];"
        :: "r"(dst), "l"(src), "r"(bytes), "r"(mbar) : "memory");
}

__global__ void k0_setup(const int* __restrict__ caps, const int* __restrict__ lens,
                         float* __restrict__ out, long long out_size) {
    int t = threadIdx.x;
    if (t == 0) {
        g_bar = 0u;
        int len[BB]; bool used[BB];
        for (int i = 0; i < BB; i++) { len[i] = lens[i]; used[i] = false; }
        for (int r = 0; r < BB; r++) {
            int best = -1;
            for (int i = 0; i < BB; i++)
                if (!used[i] && (best < 0 || len[i] > len[best])) best = i;
            used[best] = true; g_sort[r] = best; g_declen[r] = len[best] - 1;
        }
    }
    __syncthreads();
    long long P = (long long)BB * TT * VV;
    for (int i = t; i < BB*LL; i += blockDim.x) {
        int b = i / LL, c = i % LL;
        int v = caps[g_sort[b]*LL + c];
        g_caps[i] = v;
        if (P + i < out_size) out[P + i] = (float)v;
    }
    for (int i = t; i < BB; i += blockDim.x) {
        if (P + BB*LL + i      < out_size) out[P + BB*LL + i]      = (float)g_declen[i];
        if (P + BB*LL + BB + i < out_size) out[P + BB*LL + BB + i] = (float)g_sort[i];
    }
}

// convert wih + fcw to half (grid-stride)
__global__ void kc_w(const float* __restrict__ wih, const float* __restrict__ fcw) {
    const long long NW = (long long)G4 * HH;
    const long long NF = (long long)VV * HH;
    long long i = (long long)blockIdx.x * blockDim.x + threadIdx.x;
    long long stride = (long long)gridDim.x * blockDim.x;
    for (; i < NW + NF; i += stride) {
        if (i < NW) g_wih_h[i] = __float2half(wih[i]);
        else        g_fcw_h[i - NW] = __float2half(fcw[i - NW]);
    }
}

// build A-half for k4: rows 0..31 = x0bn, rows 32.. = embw[caps]. one block per row.
__global__ void kc_a4(const float* __restrict__ embw) {
    int r = blockIdx.x, t = threadIdx.x;
    const float* src;
    if (r < BB) src = g_x0bn + r * HH;
    else { int rr = r - BB; src = embw + (long long)g_caps[(rr & 31)*LL + (rr >> 5)] * HH; }
    __half* dst = g_a4h + (long long)r * HH;
    for (int i = t; i < HH; i += blockDim.x) dst[i] = __float2half(src[i]);
}

// ---- k1: x0 partials (tf32). Tile 32m x 128n, K-split 32, stage K=128 (512B rows).
__global__ __launch_bounds__(256) void k1_initgemm(const float* __restrict__ enc,
                                                   const float* __restrict__ w) {
    extern __shared__ float sm[];
    __shared__ unsigned long long mb[2];
    int t = threadIdx.x;
    int wid = t >> 5;
    int n0 = blockIdx.x * 128;
    long long kbase = (long long)blockIdx.y * KCHUNK;
    unsigned mbar[2] = { smaddr(&mb[0]), smaddr(&mb[1]) };
    if (t == 0) { mbinit(mbar[0], 1); mbinit(mbar[1], 1); }
    __syncthreads();

    const int STAGES = KCHUNK / 128;        // 98
    const unsigned STB = 160u * 512u;
    const int SST = 160 * 132;

    const float* src0 = 0;
    int drow = 0;
    if (t < 128) { src0 = w + (long long)(n0 + t) * ENCK + kbase; drow = (32 + t) * 132; }
    else if (t < 160) { src0 = enc + (long long)g_sort[t-128] * ENCK + kbase; drow = (t - 128) * 132; }

    wmma::fragment<wmma::accumulator,16,16,8,float> acc[2];
    wmma::fill_fragment(acc[0], 0.f);
    wmma::fill_fragment(acc[1], 0.f);

    if (t == 0) mexpect(mbar[0], STB);
    __syncthreads();
    if (t < 160) bulkcp(smaddr(sm + drow), src0, 512, mbar[0]);
    if (t == 0) mexpect(mbar[1], STB);
    __syncthreads();
    if (t < 160) bulkcp(smaddr(sm + SST + drow), src0 + 128, 512, mbar[1]);

    for (int s = 0; s < STAGES; s++) {
        int c = s & 1;
        mwait(mbar[c], (unsigned)((s >> 1) & 1));
        float* As = sm + c * SST;
        float* Bs = As + 32 * 132;
#pragma unroll
        for (int ks = 0; ks < 16; ks++) {
            wmma::fragment<wmma::matrix_a,16,16,8,wmma::precision::tf32,wmma::row_major> af[2];
            wmma::fragment<wmma::matrix_b,16,16,8,wmma::precision::tf32,wmma::col_major> bf;
#pragma unroll
            for (int mi = 0; mi < 2; mi++) {
                wmma::load_matrix_sync(af[mi], &As[(mi*16)*132 + ks*8], 132);
#pragma unroll
                for (int e = 0; e < af[mi].num_elements; e++)
                    af[mi].x[e] = wmma::__float_to_tf32(af[mi].x[e]);
            }
            wmma::load_matrix_sync(bf, &Bs[(wid*16)*132 + ks*8], 132);
#pragma unroll
            for (int e = 0; e < bf.num_elements; e++)
                bf.x[e] = wmma::__float_to_tf32(bf.x[e]);
            wmma::mma_sync(acc[0], af[0], bf, acc[0]);
            wmma::mma_sync(acc[1], af[1], bf, acc[1]);
        }
        __syncthreads();
        if (s + 2 < STAGES) {
            if (t == 0) mexpect(mbar[c], STB);
            __syncthreads();
            if (t < 160) bulkcp(smaddr(sm + c * SST + drow), src0 + (long long)(s+2)*128, 512, mbar[c]);
        }
    }
    float* base = g_part + (long long)blockIdx.y * BB * HH;
    wmma::store_matrix_sync(base +        n0 + wid*16, acc[0], HH, wmma::mem_row_major);
    wmma::store_matrix_sync(base + 16*HH + n0 + wid*16, acc[1], HH, wmma::mem_row_major);
}

__global__ void k2_bn(const float* __restrict__ bias, const float* __restrict__ gamma,
                      const float* __restrict__ beta) {
    int n = blockIdx.x, t = threadIdx.x;
    int b = t & 31, grp = t >> 5;
    float s = 0.f;
    for (int ks = grp; ks < KSPLIT; ks += 4)
        s += g_part[((long long)ks * BB + b) * HH + n];
    __shared__ float red[128];
    red[t] = s; __syncthreads();
    if (t < 32) {
        float x = red[t] + red[t+32] + red[t+64] + red[t+96] + bias[n];
        float sum = x, sq = x * x;
#pragma unroll
        for (int o = 16; o > 0; o >>= 1) {
            sum += __shfl_xor_sync(0xffffffffu, sum, o);
            sq  += __shfl_xor_sync(0xffffffffu, sq,  o);
        }
        float mu = sum * (1.f/32.f);
        float var = sq * (1.f/32.f) - mu * mu;
        g_x0bn[b * HH + n] = (x - mu) * rsqrtf(var + 1e-5f) * gamma[n] + beta[n];
    }
}

// ---- fp16 bulk-TMA GEMM body: tile 128m x 256n, K=512, stage K=128 halves (256B rows).
// 8 warps (2x4), warp tile 64x64, m16n16k16 half, fp32 accum. smem rows stride 136 halves.
template<typename EPI>
__device__ __forceinline__ void bulk_gemm_h(const __half* arow0, const __half* brow0,
                                            __half* smh, EPI epi) {
    __shared__ unsigned long long mb[2];
    int t = threadIdx.x;
    int wid = t >> 5, wm = wid >> 2, wn = wid & 3;
    unsigned mbar[2] = { smaddr(&mb[0]), smaddr(&mb[1]) };
    if (t == 0) { mbinit(mbar[0], 1); mbinit(mbar[1], 1); }
    __syncthreads();

    const int STAGES = HH / 128;            // 4
    const unsigned STB = 384u * 256u;       // 98304 B/stage
    const int SST = 384 * 136;              // stage stride (halves)
    int adrow = t * 136;
    int bdrow = (128 + t) * 136;

    wmma::fragment<wmma::accumulator,16,16,16,float> acc[4][4];
#pragma unroll
    for (int mi = 0; mi < 4; mi++)
#pragma unroll
        for (int nj = 0; nj < 4; nj++) wmma::fill_fragment(acc[mi][nj], 0.f);

    if (t == 0) mexpect(mbar[0], STB);
    __syncthreads();
    bulkcp(smaddr(smh + bdrow), brow0, 256, mbar[0]);
    if (t < 128) bulkcp(smaddr(smh + adrow), arow0, 256, mbar[0]);
    if (t == 0) mexpect(mbar[1], STB);
    __syncthreads();
    bulkcp(smaddr(smh + SST + bdrow), brow0 + 128, 256, mbar[1]);
    if (t < 128) bulkcp(smaddr(smh + SST + adrow), arow0 + 128, 256, mbar[1]);

    for (int s = 0; s < STAGES; s++) {
        int c = s & 1;
        mwait(mbar[c], (unsigned)((s >> 1) & 1));
        __half* As = smh + c * SST;
        __half* Bs = As + 128 * 136;
#pragma unroll
        for (int ks = 0; ks < 8; ks++) {
            wmma::fragment<wmma::matrix_a,16,16,16,__half,wmma::row_major> af[4];
            wmma::fragment<wmma::matrix_b,16,16,16,__half,wmma::col_major> bf[4];
#pragma unroll
            for (int mi = 0; mi < 4; mi++)
                wmma::load_matrix_sync(af[mi], &As[(wm*64 + mi*16)*136 + ks*16], 136);
#pragma unroll
            for (int nj = 0; nj < 4; nj++)
                wmma::load_matrix_sync(bf[nj], &Bs[(wn*64 + nj*16)*136 + ks*16], 136);
#pragma unroll
            for (int mi = 0; mi < 4; mi++)
#pragma unroll
                for (int nj = 0; nj < 4; nj++)
                    wmma::mma_sync(acc[mi][nj], af[mi], bf[nj], acc[mi][nj]);
        }
        __syncthreads();
        if (s + 2 < STAGES) {
            if (t == 0) mexpect(mbar[c], STB);
            __syncthreads();
            bulkcp(smaddr(smh + c*SST + bdrow), brow0 + (s+2)*128, 256, mbar[c]);
            if (t < 128) bulkcp(smaddr(smh + c*SST + adrow), arow0 + (s+2)*128, 256, mbar[c]);
        }
    }
    float* sC = (float*)smh;   // 128 x 260 floats (133 KB, fits in 204 KB smem)
#pragma unroll
    for (int mi = 0; mi < 4; mi++)
#pragma unroll
        for (int nj = 0; nj < 4; nj++)
            wmma::store_matrix_sync(&sC[(wm*64 + mi*16)*260 + wn*64 + nj*16],
                                    acc[mi][nj], 260, wmma::mem_row_major);
    __syncthreads();
    epi(sC);
}

// ---- k4: XW = A4h(1664x512) @ wih_h.T + bias. grid (13, 8).
__global__ __launch_bounds__(256) void k4_xw(const float* __restrict__ bih,
                                             const float* __restrict__ bhh) {
    extern __shared__ __half sm4[];
    int t = threadIdx.x;
    int m0 = blockIdx.x * 128, n0 = blockIdx.y * 256;
    const __half* arow0 = (t < 128) ? g_a4h + (long long)(m0 + t) * HH : 0;
    const __half* brow0 = g_wih_h + (long long)(n0 + t) * HH;
    bulk_gemm_h(arow0, brow0, sm4, [&](float* sC) {
#pragma unroll
        for (int j = 0; j < 128; j++) {
            int e = t + j*256;
            int row = e >> 8, cl = e & 255;
            int col = n0 + cl;
            g_xw[(long long)(m0 + row) * G4 + col] = sC[row*260 + cl] + bih[col] + bhh[col];
        }
    });
}

// ---- k5: persistent LSTM, all 52 cells, grid 128 blocks (all resident).
__global__ __launch_bounds__(128) void k5_all(const float* __restrict__ whh) {
    extern __shared__ float dyn[];
    float* hs = dyn;              // [512][32]
    float* ws = dyn + 512 * 32;   // [512][16]
    __shared__ float gs[16][33];
    int t = threadIdx.x;
    int c0 = blockIdx.x * 4;

    {
        int rl = t >> 3;
        const float* wp = whh + (long long)((rl >> 2) * 512 + c0 + (rl & 3)) * HH;
        int ko = (t & 7) * 4;
#pragma unroll
        for (int i = 0; i < 16; i++) {
            int k = ko + i * 32;
            float4 v = *(const float4*)(wp + k);
            ws[(k  )*16+rl]=v.x; ws[(k+1)*16+rl]=v.y;
            ws[(k+2)*16+rl]=v.z; ws[(k+3)*16+rl]=v.w;
        }
    }
    int eb = t & 31, ej = t >> 5;
    int ecol = c0 + ej;
    float c_reg = 0.f, h_reg = 0.f;
    int dl = g_declen[eb];
    int lb = t >> 2, ko2 = (t & 3) * 4;
    int r2 = (t & 7) * 2, b2 = (t >> 3) * 2;

    for (int cell = 0; cell < LL; cell++) {
        if (cell == 0) {
            for (int i = t; i < 512*32; i += 128) hs[i] = 0.f;
        } else {
            const float* hp = g_hbuf[cell & 1] + lb * HH;
#pragma unroll
            for (int i = 0; i < 32; i++) {
                int k = ko2 + i * 16;
                float4 v = __ldcg((const float4*)(hp + k));
                hs[(k  )*32+lb]=v.x; hs[(k+1)*32+lb]=v.y;
                hs[(k+2)*32+lb]=v.z; hs[(k+3)*32+lb]=v.w;
            }
        }
        __syncthreads();
        {
            float a00=0.f,a01=0.f,a10=0.f,a11=0.f;
#pragma unroll 8
            for (int k = 0; k < 512; k++) {
                float2 hv = *(const float2*)&hs[k*32 + b2];
                float2 wv = *(const float2*)&ws[k*16 + r2];
                a00 += hv.x*wv.x; a01 += hv.x*wv.y;
                a10 += hv.y*wv.x; a11 += hv.y*wv.y;
            }
            gs[r2  ][b2]=a00; gs[r2+1][b2]=a01;
            gs[r2  ][b2+1]=a10; gs[r2+1][b2+1]=a11;
        }
        __syncthreads();
        {
            const float* xw = g_xw + ((long long)cell * BB + eb) * G4;
            float iv = gs[0*4+ej][eb] + xw[          ecol];
            float fv = gs[1*4+ej][eb] + xw[  512 +   ecol];
            float gv = gs[2*4+ej][eb] + xw[2*512 +   ecol];
            float ov = gs[3*4+ej][eb] + xw[3*512 +   ecol];
            float si = 1.f/(1.f+expf(-iv)), sf = 1.f/(1.f+expf(-fv));
            float so = 1.f/(1.f+expf(-ov)), tg = tanhf(gv);
            float cn = sf * c_reg + si * tg;
            float hn = so * tanhf(cn);
            bool act = (cell == 0) || (dl > (cell - 1));
            c_reg = act ? cn : c_reg;
            h_reg = act ? hn : h_reg;
            int ci = eb * HH + ecol;
            g_hbuf[(cell + 1) & 1][ci] = h_reg;
            if (cell >= 1)
                g_h2h[((long long)(cell - 1) * BB + eb) * HH + ecol] = __float2half(hn);
        }
        __syncthreads();
        if (cell + 1 < LL) {
            if (t == 0) {
                __threadfence();
                atomicAdd(&g_bar, 1u);
                unsigned tgt = (unsigned)(cell + 1) * gridDim.x;
                while (*(volatile unsigned*)&g_bar < tgt) __nanosleep(64);
            }
            __syncthreads();
        }
    }
}

// ---- k6: predictions = mask( H2h(1632x512) @ fcw_h.T + fc_b ). grid (13, 40).
__global__ __launch_bounds__(256) void k6_fc(const float* __restrict__ fcb,
                                             float* __restrict__ out, long long out_size) {
    extern __shared__ __half sm6[];
    int t = threadIdx.x;
    int m0 = blockIdx.x * 128, n0 = blockIdx.y * 256;
    const int M = TT * BB;
    const __half* arow0 = 0;
    if (t < 128) {
        int r = m0 + t;
        if (r >= M) r = 0;
        arow0 = g_h2h + (long long)r * HH;
    }
    int bn = n0 + t; if (bn >= VV) bn = VV - 1;
    const __half* brow0 = g_fcw_h + (long long)bn * HH;
    bulk_gemm_h(arow0, brow0, sm6, [&](float* sC) {
#pragma unroll
        for (int j = 0; j < 128; j++) {
            int e = t + j*256;
            int row = e >> 8, cl = e & 255;
            int rr = m0 + row;
            if (rr >= M) continue;
            int col = n0 + cl;
            if (col >= VV) continue;
            int tt = rr >> 5, bb = rr & 31;
            bool act = g_declen[bb] > tt;
            long long idx = (long long)bb * TT * VV + (long long)tt * VV + col;
            if (idx < out_size)
                out[idx] = act ? (sC[row*260 + cl] + fcb[col]) : 0.f;
        }
    });
}

extern "C" void kernel_launch(void* const* d_in, const int* in_sizes, int n_in,
                              void* d_out, int out_size) {
    const float* enc   = (const float*)d_in[0];
    const int*   caps  = (const int*)  d_in[1];
    const int*   lens  = (const int*)  d_in[2];
    const float* embw  = (const float*)d_in[3];
    const float* initw = (const float*)d_in[4];
    const float* initb = (const float*)d_in[5];
    const float* gamma = (const float*)d_in[6];
    const float* beta  = (const float*)d_in[7];
    const float* wih   = (const float*)d_in[8];
    const float* whh   = (const float*)d_in[9];
    const float* bih   = (const float*)d_in[10];
    const float* bhh   = (const float*)d_in[11];
    const float* fcw   = (const float*)d_in[12];
    const float* fcb   = (const float*)d_in[13];
    float* out = (float*)d_out;
    long long osz = (long long)out_size;

    const int SM1  = 2 * 160 * 132 * 4;        // 168,960 B (k1, fp32 tiles)
    const int SMGH = 2 * 384 * 136 * 2;        // 208,896 B (k4/k6 half tiles; epilogue reuse)
    const int SM5  = (512*32 + 512*16) * 4;    // 98,304 B
    cudaFuncSetAttribute(k1_initgemm, cudaFuncAttributeMaxDynamicSharedMemorySize, SM1);
    cudaFuncSetAttribute(k4_xw,       cudaFuncAttributeMaxDynamicSharedMemorySize, SMGH);
    cudaFuncSetAttribute(k6_fc,       cudaFuncAttributeMaxDynamicSharedMemorySize, SMGH);
    cudaFuncSetAttribute(k5_all,      cudaFuncAttributeMaxDynamicSharedMemorySize, SM5);

    k0_setup<<<1, 256>>>(caps, lens, out, osz);
    kc_w<<<592, 256>>>(wih, fcw);
    k1_initgemm<<<dim3(4, KSPLIT), 256, SM1>>>(enc, initw);
    k2_bn<<<512, 128>>>(initb, gamma, beta);
    kc_a4<<<MROWS, 128>>>(embw);
    k4_xw<<<dim3(13, 8), 256, SMGH>>>(bih, bhh);
    k5_all<<<128, 128, SM5>>>(whh);
    k6_fc<<<dim3(13, 40), 256, SMGH>>>(fcb, out, osz);
}

// round 10
// speedup vs baseline: 1.8627x; 1.0752x over previous
#include <cuda_runtime.h>
#include <cuda_fp16.h>
#include <mma.h>
#include <math.h>

using namespace nvcuda;

#define BB 32
#define LL 52
#define VV 10000
#define HH 512
#define ENCK 401408
#define TT 51
#define G4 2048
#define KSPLIT 64
#define KCHUNK 6272    /* 64 * 6272 = 401408 exact */
#define MROWS 1664     /* 32 + 51*32 */
#define PLD 72         /* k5 partial stride: multiple of 4 floats (wmma ldm rule) */

__device__ int   g_sort[BB];
__device__ int   g_declen[BB];
__device__ int   g_caps[BB*LL];
__device__ float g_part[(long long)KSPLIT*BB*HH];
__device__ float g_x0bn[BB*HH];
__device__ float g_xw[(long long)LL*BB*G4];
__device__ float g_hbuf[2][BB*HH];
__device__ unsigned g_bar;
__device__ __half g_wih_h[(long long)G4*HH];
__device__ __half g_fcw_h[(long long)VV*HH];
__device__ __half g_a4h[(long long)MROWS*HH];
__device__ __half g_h2h[(long long)TT*BB*HH];

// ---------------- TMA 1D bulk + mbarrier helpers ----------------
__device__ __forceinline__ unsigned smaddr(const void* p) {
    return (unsigned)__cvta_generic_to_shared(p);
}
__device__ __forceinline__ void mbinit(unsigned mbar, unsigned cnt) {
    asm volatile("mbarrier.init.shared.b64 [%0], %1;" :: "r"(mbar), "r"(cnt) : "memory");
}
__device__ __forceinline__ void mexpect(unsigned mbar, unsigned bytes) {
    asm volatile("mbarrier.arrive.expect_tx.shared.b64 _, [%0], %1;"
                 :: "r"(mbar), "r"(bytes) : "memory");
}
__device__ __forceinline__ void mwait(unsigned mbar, unsigned parity) {
    asm volatile(
        "{\n\t.reg .pred P;\n\t"
        "LW%=:\n\t"
        "mbarrier.try_wait.parity.acquire.cta.shared::cta.b64 P, [%0], %1, 0x989680;\n\t"
        "@P bra LD%=;\n\t"
        "bra LW%=;\n\t"
        "LD%=:\n\t}"
        :: "r"(mbar), "r"(parity) : "memory");
}
__device__ __forceinline__ void bulkcp(unsigned dst, const void* src, unsigned bytes, unsigned mbar) {
    asm volatile(
        "cp.async.bulk.shared::cluster.global.mbarrier::complete_tx::bytes [%0], [%1], %2, [%3];"
        :: "r"(dst), "l"(src), "r"(bytes), "r"(mbar) : "memory");
}

__global__ void k0_setup(const int* __restrict__ caps, const int* __restrict__ lens,
                         float* __restrict__ out, long long out_size) {
    int t = threadIdx.x;
    if (t == 0) {
        g_bar = 0u;
        int len[BB]; bool used[BB];
        for (int i = 0; i < BB; i++) { len[i] = lens[i]; used[i] = false; }
        for (int r = 0; r < BB; r++) {
            int best = -1;
            for (int i = 0; i < BB; i++)
                if (!used[i] && (best < 0 || len[i] > len[best])) best = i;
            used[best] = true; g_sort[r] = best; g_declen[r] = len[best] - 1;
        }
    }
    __syncthreads();
    long long P = (long long)BB * TT * VV;
    for (int i = t; i < BB*LL; i += blockDim.x) {
        int b = i / LL, c = i % LL;
        int v = caps[g_sort[b]*LL + c];
        g_caps[i] = v;
        if (P + i < out_size) out[P + i] = (float)v;
    }
    for (int i = t; i < BB; i += blockDim.x) {
        if (P + BB*LL + i      < out_size) out[P + BB*LL + i]      = (float)g_declen[i];
        if (P + BB*LL + BB + i < out_size) out[P + BB*LL + BB + i] = (float)g_sort[i];
    }
}

// convert wih + fcw to half (grid-stride)
__global__ void kc_w(const float* __restrict__ wih, const float* __restrict__ fcw) {
    const long long NW = (long long)G4 * HH;
    const long long NF = (long long)VV * HH;
    long long i = (long long)blockIdx.x * blockDim.x + threadIdx.x;
    long long stride = (long long)gridDim.x * blockDim.x;
    for (; i < NW + NF; i += stride) {
        if (i < NW) g_wih_h[i] = __float2half(wih[i]);
        else        g_fcw_h[i - NW] = __float2half(fcw[i - NW]);
    }
}

// build A-half for k4: rows 0..31 = x0bn, rows 32.. = embw[caps]. one block per row.
__global__ void kc_a4(const float* __restrict__ embw) {
    int r = blockIdx.x, t = threadIdx.x;
    const float* src;
    if (r < BB) src = g_x0bn + r * HH;
    else { int rr = r - BB; src = embw + (long long)g_caps[(rr & 31)*LL + (rr >> 5)] * HH; }
    __half* dst = g_a4h + (long long)r * HH;
    for (int i = t; i < HH; i += blockDim.x) dst[i] = __float2half(src[i]);
}

// ---- k1: x0 partials (tf32). Tile 32m x 256n, K-split 64, stage K=64 (256B rows).
__global__ __launch_bounds__(256) void k1_initgemm(const float* __restrict__ enc,
                                                   const float* __restrict__ w) {
    extern __shared__ float sm[];
    __shared__ unsigned long long mb[2];
    int t = threadIdx.x;
    int wid = t >> 5;
    int n0 = blockIdx.x * 256;
    long long kbase = (long long)blockIdx.y * KCHUNK;
    unsigned mbar[2] = { smaddr(&mb[0]), smaddr(&mb[1]) };
    if (t == 0) { mbinit(mbar[0], 1); mbinit(mbar[1], 1); }
    __syncthreads();

    const int STAGES = KCHUNK / 64;         // 98
    const unsigned STB = 288u * 256u;
    const int SST = 288 * 68;

    const float* bsrc = w + (long long)(n0 + t) * ENCK + kbase;
    int bdrow = (32 + t) * 68;
    const float* asrc = (t < 32) ? enc + (long long)g_sort[t] * ENCK + kbase : 0;
    int adrow = t * 68;

    wmma::fragment<wmma::accumulator,16,16,8,float> acc[2][2];
#pragma unroll
    for (int mi = 0; mi < 2; mi++)
#pragma unroll
        for (int nj = 0; nj < 2; nj++) wmma::fill_fragment(acc[mi][nj], 0.f);

    if (t == 0) mexpect(mbar[0], STB);
    __syncthreads();
    bulkcp(smaddr(sm + bdrow), bsrc, 256, mbar[0]);
    if (t < 32) bulkcp(smaddr(sm + adrow), asrc, 256, mbar[0]);
    if (t == 0) mexpect(mbar[1], STB);
    __syncthreads();
    bulkcp(smaddr(sm + SST + bdrow), bsrc + 64, 256, mbar[1]);
    if (t < 32) bulkcp(smaddr(sm + SST + adrow), asrc + 64, 256, mbar[1]);

    for (int s = 0; s < STAGES; s++) {
        int c = s & 1;
        mwait(mbar[c], (unsigned)((s >> 1) & 1));
        float* As = sm + c * SST;
        float* Bs = As + 32 * 68;
#pragma unroll
        for (int ks = 0; ks < 8; ks++) {
            wmma::fragment<wmma::matrix_a,16,16,8,wmma::precision::tf32,wmma::row_major> af[2];
            wmma::fragment<wmma::matrix_b,16,16,8,wmma::precision::tf32,wmma::col_major> bf[2];
#pragma unroll
            for (int mi = 0; mi < 2; mi++) {
                wmma::load_matrix_sync(af[mi], &As[(mi*16)*68 + ks*8], 68);
#pragma unroll
                for (int e = 0; e < af[mi].num_elements; e++)
                    af[mi].x[e] = wmma::__float_to_tf32(af[mi].x[e]);
            }
#pragma unroll
            for (int nj = 0; nj < 2; nj++) {
                wmma::load_matrix_sync(bf[nj], &Bs[(wid*32 + nj*16)*68 + ks*8], 68);
#pragma unroll
                for (int e = 0; e < bf[nj].num_elements; e++)
                    bf[nj].x[e] = wmma::__float_to_tf32(bf[nj].x[e]);
            }
#pragma unroll
            for (int mi = 0; mi < 2; mi++)
#pragma unroll
                for (int nj = 0; nj < 2; nj++)
                    wmma::mma_sync(acc[mi][nj], af[mi], bf[nj], acc[mi][nj]);
        }
        __syncthreads();
        if (s + 2 < STAGES) {
            if (t == 0) mexpect(mbar[c], STB);
            __syncthreads();
            bulkcp(smaddr(sm + c*SST + bdrow), bsrc + (long long)(s+2)*64, 256, mbar[c]);
            if (t < 32) bulkcp(smaddr(sm + c*SST + adrow), asrc + (long long)(s+2)*64, 256, mbar[c]);
        }
    }
    float* base = g_part + (long long)blockIdx.y * BB * HH;
#pragma unroll
    for (int mi = 0; mi < 2; mi++)
#pragma unroll
        for (int nj = 0; nj < 2; nj++)
            wmma::store_matrix_sync(base + mi*16*HH + n0 + wid*32 + nj*16,
                                    acc[mi][nj], HH, wmma::mem_row_major);
}

__global__ void k2_bn(const float* __restrict__ bias, const float* __restrict__ gamma,
                      const float* __restrict__ beta) {
    int n = blockIdx.x, t = threadIdx.x;
    int b = t & 31, grp = t >> 5;
    float s = 0.f;
    for (int ks = grp; ks < KSPLIT; ks += 4)
        s += g_part[((long long)ks * BB + b) * HH + n];
    __shared__ float red[128];
    red[t] = s; __syncthreads();
    if (t < 32) {
        float x = red[t] + red[t+32] + red[t+64] + red[t+96] + bias[n];
        float sum = x, sq = x * x;
#pragma unroll
        for (int o = 16; o > 0; o >>= 1) {
            sum += __shfl_xor_sync(0xffffffffu, sum, o);
            sq  += __shfl_xor_sync(0xffffffffu, sq,  o);
        }
        float mu = sum * (1.f/32.f);
        float var = sq * (1.f/32.f) - mu * mu;
        g_x0bn[b * HH + n] = (x - mu) * rsqrtf(var + 1e-5f) * gamma[n] + beta[n];
    }
}

// ---- fp16 bulk-TMA GEMM body: tile 128m x 256n, K=512, stage K=128 halves (256B rows).
template<typename EPI>
__device__ __forceinline__ void bulk_gemm_h(const __half* arow0, const __half* brow0,
                                            __half* smh, EPI epi) {
    __shared__ unsigned long long mb[2];
    int t = threadIdx.x;
    int wid = t >> 5, wm = wid >> 2, wn = wid & 3;
    unsigned mbar[2] = { smaddr(&mb[0]), smaddr(&mb[1]) };
    if (t == 0) { mbinit(mbar[0], 1); mbinit(mbar[1], 1); }
    __syncthreads();

    const int STAGES = HH / 128;            // 4
    const unsigned STB = 384u * 256u;
    const int SST = 384 * 136;
    int adrow = t * 136;
    int bdrow = (128 + t) * 136;

    wmma::fragment<wmma::accumulator,16,16,16,float> acc[4][4];
#pragma unroll
    for (int mi = 0; mi < 4; mi++)
#pragma unroll
        for (int nj = 0; nj < 4; nj++) wmma::fill_fragment(acc[mi][nj], 0.f);

    if (t == 0) mexpect(mbar[0], STB);
    __syncthreads();
    bulkcp(smaddr(smh + bdrow), brow0, 256, mbar[0]);
    if (t < 128) bulkcp(smaddr(smh + adrow), arow0, 256, mbar[0]);
    if (t == 0) mexpect(mbar[1], STB);
    __syncthreads();
    bulkcp(smaddr(smh + SST + bdrow), brow0 + 128, 256, mbar[1]);
    if (t < 128) bulkcp(smaddr(smh + SST + adrow), arow0 + 128, 256, mbar[1]);

    for (int s = 0; s < STAGES; s++) {
        int c = s & 1;
        mwait(mbar[c], (unsigned)((s >> 1) & 1));
        __half* As = smh + c * SST;
        __half* Bs = As + 128 * 136;
#pragma unroll
        for (int ks = 0; ks < 8; ks++) {
            wmma::fragment<wmma::matrix_a,16,16,16,__half,wmma::row_major> af[4];
            wmma::fragment<wmma::matrix_b,16,16,16,__half,wmma::col_major> bf[4];
#pragma unroll
            for (int mi = 0; mi < 4; mi++)
                wmma::load_matrix_sync(af[mi], &As[(wm*64 + mi*16)*136 + ks*16], 136);
#pragma unroll
            for (int nj = 0; nj < 4; nj++)
                wmma::load_matrix_sync(bf[nj], &Bs[(wn*64 + nj*16)*136 + ks*16], 136);
#pragma unroll
            for (int mi = 0; mi < 4; mi++)
#pragma unroll
                for (int nj = 0; nj < 4; nj++)
                    wmma::mma_sync(acc[mi][nj], af[mi], bf[nj], acc[mi][nj]);
        }
        __syncthreads();
        if (s + 2 < STAGES) {
            if (t == 0) mexpect(mbar[c], STB);
            __syncthreads();
            bulkcp(smaddr(smh + c*SST + bdrow), brow0 + (s+2)*128, 256, mbar[c]);
            if (t < 128) bulkcp(smaddr(smh + c*SST + adrow), arow0 + (s+2)*128, 256, mbar[c]);
        }
    }
    float* sC = (float*)smh;
#pragma unroll
    for (int mi = 0; mi < 4; mi++)
#pragma unroll
        for (int nj = 0; nj < 4; nj++)
            wmma::store_matrix_sync(&sC[(wm*64 + mi*16)*260 + wn*64 + nj*16],
                                    acc[mi][nj], 260, wmma::mem_row_major);
    __syncthreads();
    epi(sC);
}

// ---- k4: XW = A4h(1664x512) @ wih_h.T + bias. grid (13, 8).
__global__ __launch_bounds__(256) void k4_xw(const float* __restrict__ bih,
                                             const float* __restrict__ bhh) {
    extern __shared__ __half sm4[];
    int t = threadIdx.x;
    int m0 = blockIdx.x * 128, n0 = blockIdx.y * 256;
    const __half* arow0 = (t < 128) ? g_a4h + (long long)(m0 + t) * HH : 0;
    const __half* brow0 = g_wih_h + (long long)(n0 + t) * HH;
    bulk_gemm_h(arow0, brow0, sm4, [&](float* sC) {
#pragma unroll
        for (int j = 0; j < 128; j++) {
            int e = t + j*256;
            int row = e >> 8, cl = e & 255;
            int col = n0 + cl;
            g_xw[(long long)(m0 + row) * G4 + col] = sC[row*260 + cl] + bih[col] + bhh[col];
        }
    });
}

// ---- k5: persistent LSTM via fp16 wmma. 32 blocks x 128 thr; block owns 16 h-cols.
__global__ __launch_bounds__(128) void k5_all(const float* __restrict__ whh) {
    extern __shared__ __half smh5[];
    __half* Bs = smh5;                      // [64][520]
    __half* Ah = smh5 + 64*520;             // [32][520]
    float*  sP = (float*)(smh5 + 96*520);   // [4][32][PLD]
    int t = threadIdx.x;
    int w = t >> 5;
    int c0 = blockIdx.x * 16;

    {   // convert whh slice to fp16 smem once: row r = g*16+j <-> whh row g*512+c0+j
        int r = t >> 1, g = r >> 4, j = r & 15;
        const float* wp = whh + (long long)(g*512 + c0 + j) * HH + (t & 1) * 256;
        __half* dst = Bs + r*520 + (t & 1) * 256;
#pragma unroll 8
        for (int i = 0; i < 64; i++) {
            float4 v = *(const float4*)(wp + i*4);
            *(__half2*)(dst + i*4)     = __floats2half2_rn(v.x, v.y);
            *(__half2*)(dst + i*4 + 2) = __floats2half2_rn(v.z, v.w);
        }
    }
    {   // zero Ah (cell 0 uses h=0)
        unsigned* az = (unsigned*)Ah;
        for (int i = t; i < 32*520/2; i += 128) az[i] = 0u;
    }

    int eb = t & 31;
    float c_reg[4] = {0.f,0.f,0.f,0.f}, h_reg[4] = {0.f,0.f,0.f,0.f};
    int dl = g_declen[eb];
    int hb = t >> 2, hq = (t & 3) * 128;

    for (int cell = 0; cell < LL; cell++) {
        if (cell > 0) {
            const float* hp = g_hbuf[cell & 1] + hb * HH + hq;
            __half* dst = Ah + hb*520 + hq;
#pragma unroll 8
            for (int i = 0; i < 32; i++) {
                float4 v = __ldcg((const float4*)(hp + i*4));
                *(__half2*)(dst + i*4)     = __floats2half2_rn(v.x, v.y);
                *(__half2*)(dst + i*4 + 2) = __floats2half2_rn(v.z, v.w);
            }
        }
        __syncthreads();
        {   // GEMM: warp w covers k in [w*128, w*128+128), acc m32 x n64
            wmma::fragment<wmma::accumulator,16,16,16,float> acc[2][4];
#pragma unroll
            for (int mi = 0; mi < 2; mi++)
#pragma unroll
                for (int nj = 0; nj < 4; nj++) wmma::fill_fragment(acc[mi][nj], 0.f);
            int kw = w * 128;
#pragma unroll
            for (int ks = 0; ks < 8; ks++) {
                wmma::fragment<wmma::matrix_a,16,16,16,__half,wmma::row_major> af[2];
                wmma::fragment<wmma::matrix_b,16,16,16,__half,wmma::col_major> bf[4];
#pragma unroll
                for (int mi = 0; mi < 2; mi++)
                    wmma::load_matrix_sync(af[mi], &Ah[(mi*16)*520 + kw + ks*16], 520);
#pragma unroll
                for (int nj = 0; nj < 4; nj++)
                    wmma::load_matrix_sync(bf[nj], &Bs[(nj*16)*520 + kw + ks*16], 520);
#pragma unroll
                for (int mi = 0; mi < 2; mi++)
#pragma unroll
                    for (int nj = 0; nj < 4; nj++)
                        wmma::mma_sync(acc[mi][nj], af[mi], bf[nj], acc[mi][nj]);
            }
            float* sPw = sP + w * 32 * PLD;
#pragma unroll
            for (int mi = 0; mi < 2; mi++)
#pragma unroll
                for (int nj = 0; nj < 4; nj++)
                    wmma::store_matrix_sync(&sPw[(mi*16)*PLD + nj*16],
                                            acc[mi][nj], PLD, wmma::mem_row_major);
        }
        __syncthreads();
        {   // reduce partials + elementwise. thread: (eb, j = w*4+jj)
            const float* xw = g_xw + ((long long)cell * BB + eb) * G4;
#pragma unroll
            for (int jj = 0; jj < 4; jj++) {
                int j = w * 4 + jj;
                int col = c0 + j;
                float gv4[4];
#pragma unroll
                for (int g = 0; g < 4; g++) {
                    int n = g * 16 + j;
                    float s = sP[0*32*PLD + eb*PLD + n] + sP[1*32*PLD + eb*PLD + n]
                            + sP[2*32*PLD + eb*PLD + n] + sP[3*32*PLD + eb*PLD + n];
                    gv4[g] = s + xw[g*512 + col];
                }
                float si = 1.f/(1.f+expf(-gv4[0])), sf = 1.f/(1.f+expf(-gv4[1]));
                float tg = tanhf(gv4[2]),           so = 1.f/(1.f+expf(-gv4[3]));
                float cn = sf * c_reg[jj] + si * tg;
                float hn = so * tanhf(cn);
                bool act = (cell == 0) || (dl > (cell - 1));
                c_reg[jj] = act ? cn : c_reg[jj];
                h_reg[jj] = act ? hn : h_reg[jj];
                g_hbuf[(cell + 1) & 1][eb * HH + col] = h_reg[jj];
                if (cell >= 1)
                    g_h2h[((long long)(cell - 1) * BB + eb) * HH + col] = __float2half(hn);
            }
        }
        __syncthreads();
        if (cell + 1 < LL) {
            if (t == 0) {
                __threadfence();
                atomicAdd(&g_bar, 1u);
                unsigned tgt = (unsigned)(cell + 1) * gridDim.x;
                while (*(volatile unsigned*)&g_bar < tgt) __nanosleep(64);
            }
            __syncthreads();
        }
    }
}

// ---- k6: predictions = mask( H2h(1632x512) @ fcw_h.T + fc_b ). grid (13, 40).
__global__ __launch_bounds__(256) void k6_fc(const float* __restrict__ fcb,
                                             float* __restrict__ out, long long out_size) {
    extern __shared__ __half sm6[];
    int t = threadIdx.x;
    int m0 = blockIdx.x * 128, n0 = blockIdx.y * 256;
    const int M = TT * BB;
    const __half* arow0 = 0;
    if (t < 128) {
        int r = m0 + t;
        if (r >= M) r = 0;
        arow0 = g_h2h + (long long)r * HH;
    }
    int bn = n0 + t; if (bn >= VV) bn = VV - 1;
    const __half* brow0 = g_fcw_h + (long long)bn * HH;
    bulk_gemm_h(arow0, brow0, sm6, [&](float* sC) {
#pragma unroll
        for (int j = 0; j < 128; j++) {
            int e = t + j*256;
            int row = e >> 8, cl = e & 255;
            int rr = m0 + row;
            if (rr >= M) continue;
            int col = n0 + cl;
            if (col >= VV) continue;
            int tt = rr >> 5, bb = rr & 31;
            bool act = g_declen[bb] > tt;
            long long idx = (long long)bb * TT * VV + (long long)tt * VV + col;
            if (idx < out_size)
                out[idx] = act ? (sC[row*260 + cl] + fcb[col]) : 0.f;
        }
    });
}

extern "C" void kernel_launch(void* const* d_in, const int* in_sizes, int n_in,
                              void* d_out, int out_size) {
    const float* enc   = (const float*)d_in[0];
    const int*   caps  = (const int*)  d_in[1];
    const int*   lens  = (const int*)  d_in[2];
    const float* embw  = (const float*)d_in[3];
    const float* initw = (const float*)d_in[4];
    const float* initb = (const float*)d_in[5];
    const float* gamma = (const float*)d_in[6];
    const float* beta  = (const float*)d_in[7];
    const float* wih   = (const float*)d_in[8];
    const float* whh   = (const float*)d_in[9];
    const float* bih   = (const float*)d_in[10];
    const float* bhh   = (const float*)d_in[11];
    const float* fcw   = (const float*)d_in[12];
    const float* fcb   = (const float*)d_in[13];
    float* out = (float*)d_out;
    long long osz = (long long)out_size;

    const int SM1  = 2 * 288 * 68 * 4;          // 156,672 B
    const int SMGH = 2 * 384 * 136 * 2;         // 208,896 B
    const int SM5  = 96*520*2 + 4*32*PLD*4;     // 99,840 + 36,864 = 136,704 B
    cudaFuncSetAttribute(k1_initgemm, cudaFuncAttributeMaxDynamicSharedMemorySize, SM1);
    cudaFuncSetAttribute(k4_xw,       cudaFuncAttributeMaxDynamicSharedMemorySize, SMGH);
    cudaFuncSetAttribute(k6_fc,       cudaFuncAttributeMaxDynamicSharedMemorySize, SMGH);
    cudaFuncSetAttribute(k5_all,      cudaFuncAttributeMaxDynamicSharedMemorySize, SM5);

    k0_setup<<<1, 256>>>(caps, lens, out, osz);
    kc_w<<<592, 256>>>(wih, fcw);
    k1_initgemm<<<dim3(2, KSPLIT), 256, SM1>>>(enc, initw);
    k2_bn<<<512, 128>>>(initb, gamma, beta);
    kc_a4<<<MROWS, 128>>>(embw);
    k4_xw<<<dim3(13, 8), 256, SMGH>>>(bih, bhh);
    k5_all<<<32, 128, SM5>>>(whh);
    k6_fc<<<dim3(13, 40), 256, SMGH>>>(fcb, out, osz);
}